// round 1
// baseline (speedup 1.0000x reference)
#include <cuda_runtime.h>
#include <math_constants.h>

#define BSZ 2
#define TLEN 2048
#define DMODEL 1024
#define HN 16
#define DHEAD 64

// Q scratch in [B, H, T, DH] layout (16 MB) — __device__ global per allocation rules.
__device__ float g_q[BSZ * HN * TLEN * DHEAD];

// ---------------------------------------------------------------------------
// Kernel 1: Q projection GEMM.
// q[b,h,t,dh] = sum_d x[b,t,d] * Wq[h*DH+dh, d]     (y = x @ Wq^T)
// Tiled 64x64 output tile, K-tile 16, 256 threads, 4x4 per thread.
// ---------------------------------------------------------------------------
__global__ __launch_bounds__(256) void qgemm_kernel(const float* __restrict__ x,
                                                    const float* __restrict__ Wq) {
    __shared__ float As[16][64];  // As[kk][m]
    __shared__ float Bs[16][64];  // Bs[kk][n]

    const int tid = threadIdx.x;
    const int tx = tid & 15;       // 0..15 (cols)
    const int ty = tid >> 4;       // 0..15 (rows)
    const int m0 = blockIdx.y * 64;
    const int n0 = blockIdx.x * 64;

    float acc[4][4];
#pragma unroll
    for (int i = 0; i < 4; i++)
#pragma unroll
        for (int j = 0; j < 4; j++) acc[i][j] = 0.f;

    for (int k0 = 0; k0 < DMODEL; k0 += 16) {
        // Cooperative load: 1024 floats each for A and B tiles, 4 per thread.
#pragma unroll
        for (int i = 0; i < 4; i++) {
            int idx = tid + i * 256;
            int mm = idx >> 4;
            int kk = idx & 15;
            As[kk][mm] = x[(m0 + mm) * DMODEL + k0 + kk];
            Bs[kk][mm] = Wq[(n0 + mm) * DMODEL + k0 + kk];
        }
        __syncthreads();

#pragma unroll
        for (int kk = 0; kk < 16; kk++) {
            float a[4], bb[4];
#pragma unroll
            for (int i = 0; i < 4; i++) a[i] = As[kk][ty * 4 + i];
#pragma unroll
            for (int j = 0; j < 4; j++) bb[j] = Bs[kk][tx * 4 + j];
#pragma unroll
            for (int i = 0; i < 4; i++)
#pragma unroll
                for (int j = 0; j < 4; j++) acc[i][j] += a[i] * bb[j];
        }
        __syncthreads();
    }

    // Write to g_q in [B,H,T,DH] layout.
#pragma unroll
    for (int i = 0; i < 4; i++) {
        int m = m0 + ty * 4 + i;      // m = b*TLEN + t
        int b = m >> 11;              // / 2048
        int t = m & (TLEN - 1);
#pragma unroll
        for (int j = 0; j < 4; j++) {
            int n = n0 + tx * 4 + j;  // n = h*DHEAD + dh
            int h = n >> 6;
            int dh = n & 63;
            g_q[(((b * HN + h) * TLEN + t) * DHEAD) + dh] = acc[i][j];
        }
    }
}

// ---------------------------------------------------------------------------
// Kernel 2: causal flash attention + residual.
// Grid: (T/64, H, B). 64 threads per block; thread owns one query row.
// Q row and O accumulator in registers; K/V 64x64 tiles in smem (broadcast
// reads -> conflict-free). Online softmax in 32-key chunks to limit live regs.
// ---------------------------------------------------------------------------
__global__ __launch_bounds__(64) void attn_kernel(const float* __restrict__ x,
                                                  const float* __restrict__ k,
                                                  const float* __restrict__ v,
                                                  float* __restrict__ out) {
    __shared__ float Ks[64 * DHEAD];
    __shared__ float Vs[64 * DHEAD];

    const int tid = threadIdx.x;
    const int qtile = blockIdx.x;   // 0..31
    const int h = blockIdx.y;
    const int b = blockIdx.z;
    const int qr = qtile * 64 + tid;  // global query row

    const float scale = 0.03125f;     // 1/sqrt(1024)

    float qv[DHEAD], o[DHEAD];
    {
        const float4* qp = (const float4*)(g_q + (((b * HN + h) * TLEN) + qr) * DHEAD);
#pragma unroll
        for (int i = 0; i < 16; i++) {
            float4 t4 = qp[i];
            qv[4 * i + 0] = t4.x; qv[4 * i + 1] = t4.y;
            qv[4 * i + 2] = t4.z; qv[4 * i + 3] = t4.w;
        }
    }
#pragma unroll
    for (int d = 0; d < DHEAD; d++) o[d] = 0.f;

    float mrow = -CUDART_INF_F;
    float lrow = 0.f;

    const float* kbase = k + (size_t)((b * HN + h) * TLEN) * DHEAD;
    const float* vbase = v + (size_t)((b * HN + h) * TLEN) * DHEAD;

    for (int kt = 0; kt <= qtile; kt++) {
        // Load K/V tile (4096 floats each): 16 float4 per thread, coalesced.
        const float4* kg = (const float4*)(kbase + kt * 64 * DHEAD);
        const float4* vg = (const float4*)(vbase + kt * 64 * DHEAD);
        float4* Ks4 = (float4*)Ks;
        float4* Vs4 = (float4*)Vs;
#pragma unroll
        for (int i = 0; i < 16; i++) {
            Ks4[tid + i * 64] = kg[tid + i * 64];
            Vs4[tid + i * 64] = vg[tid + i * 64];
        }
        __syncthreads();

        const bool diag = (kt == qtile);

        // Process the 64-key tile in two 32-key chunks (caps live s[] regs).
#pragma unroll
        for (int half = 0; half < 2; half++) {
            const int jbase = half * 32;
            float s[32];
#pragma unroll
            for (int j = 0; j < 32; j++) {
                const float4* kr = (const float4*)(Ks + (jbase + j) * DHEAD);
                float ax = 0.f, ay = 0.f, az = 0.f, aw = 0.f;
#pragma unroll
                for (int i = 0; i < 16; i++) {
                    float4 k4 = kr[i];
                    ax += qv[4 * i + 0] * k4.x;
                    ay += qv[4 * i + 1] * k4.y;
                    az += qv[4 * i + 2] * k4.z;
                    aw += qv[4 * i + 3] * k4.w;
                }
                s[j] = (ax + ay) + (az + aw);
            }

            float tmax = -CUDART_INF_F;
#pragma unroll
            for (int j = 0; j < 32; j++) {
                float sv = s[j] * scale;
                if (diag && (kt * 64 + jbase + j > qr)) sv = -CUDART_INF_F;
                s[j] = sv;
                tmax = fmaxf(tmax, sv);
            }

            float mnew = fmaxf(mrow, tmax);
            if (mnew != -CUDART_INF_F) {   // chunk fully masked -> skip (keeps exp args finite)
                float corr = __expf(mrow - mnew);  // exp(-inf)=0 on first chunk
                lrow *= corr;
#pragma unroll
                for (int d = 0; d < DHEAD; d++) o[d] *= corr;

#pragma unroll
                for (int j = 0; j < 32; j++) {
                    float p = __expf(s[j] - mnew);
                    lrow += p;
                    const float4* vr = (const float4*)(Vs + (jbase + j) * DHEAD);
#pragma unroll
                    for (int i = 0; i < 16; i++) {
                        float4 v4 = vr[i];
                        o[4 * i + 0] += p * v4.x;
                        o[4 * i + 1] += p * v4.y;
                        o[4 * i + 2] += p * v4.z;
                        o[4 * i + 3] += p * v4.w;
                    }
                }
                mrow = mnew;
            }
        }
        __syncthreads();
    }

    // Residual add + write out slice [b, qr, h*64 .. h*64+63].
    const float inv = 1.f / lrow;
    const float* xp = x + (size_t)(b * TLEN + qr) * DMODEL + h * DHEAD;
    float* op = out + (size_t)(b * TLEN + qr) * DMODEL + h * DHEAD;
#pragma unroll
    for (int i = 0; i < 16; i++) {
        float4 x4 = ((const float4*)xp)[i];
        float4 r;
        r.x = x4.x + o[4 * i + 0] * inv;
        r.y = x4.y + o[4 * i + 1] * inv;
        r.z = x4.z + o[4 * i + 2] * inv;
        r.w = x4.w + o[4 * i + 3] * inv;
        ((float4*)op)[i] = r;
    }
}

extern "C" void kernel_launch(void* const* d_in, const int* in_sizes, int n_in,
                              void* d_out, int out_size) {
    const float* x  = (const float*)d_in[0];   // [B,T,D]
    const float* k  = (const float*)d_in[1];   // [B,H,T,DH]
    const float* v  = (const float*)d_in[2];   // [B,H,T,DH]
    const float* Wq = (const float*)d_in[3];   // [D,D]
    float* out = (float*)d_out;                // [B,T,D]

    dim3 g1(DMODEL / 64, (BSZ * TLEN) / 64);   // (16, 64)
    qgemm_kernel<<<g1, 256>>>(x, Wq);

    dim3 g2(TLEN / 64, HN, BSZ);               // (32, 16, 2)
    attn_kernel<<<g2, 64>>>(x, k, v, out);
}

// round 2
// speedup vs baseline: 2.2215x; 2.2215x over previous
#include <cuda_runtime.h>
#include <math_constants.h>

#define BSZ 2
#define TLEN 2048
#define DMODEL 1024
#define HN 16
#define DHEAD 64

// Q scratch in [B, H, T, DH] layout (16 MB).
__device__ float g_q[BSZ * HN * TLEN * DHEAD];

// ---------------------------------------------------------------------------
// Kernel 1: Q projection GEMM.  q = x @ Wq^T, written as [B,H,T,DH].
// 128x128 output tile, K-tile 16, 256 threads, 8x8 per thread.
// ---------------------------------------------------------------------------
__global__ __launch_bounds__(256) void qgemm_kernel(const float* __restrict__ x,
                                                    const float* __restrict__ Wq) {
    __shared__ float As[16][128];  // As[k][m]
    __shared__ float Bs[16][128];  // Bs[k][n]

    const int tid = threadIdx.x;
    const int tx = tid & 15;       // 0..15
    const int ty = tid >> 4;       // 0..15
    const int m0 = blockIdx.y * 128;
    const int n0 = blockIdx.x * 128;

    float acc[8][8];
#pragma unroll
    for (int i = 0; i < 8; i++)
#pragma unroll
        for (int j = 0; j < 8; j++) acc[i][j] = 0.f;

    // Per thread: 2 float4 of A and 2 of B per K-tile.
    const int lr = tid >> 1;          // row within tile (0..127)
    const int lc = tid & 1;           // which 8-float half of the 16 K values

    for (int k0 = 0; k0 < DMODEL; k0 += 16) {
#pragma unroll
        for (int q = 0; q < 2; q++) {
            int kk = lc * 8 + q * 4;
            float4 a4 = *(const float4*)(x  + (size_t)(m0 + lr) * DMODEL + k0 + kk);
            float4 b4 = *(const float4*)(Wq + (size_t)(n0 + lr) * DMODEL + k0 + kk);
            As[kk + 0][lr] = a4.x; As[kk + 1][lr] = a4.y;
            As[kk + 2][lr] = a4.z; As[kk + 3][lr] = a4.w;
            Bs[kk + 0][lr] = b4.x; Bs[kk + 1][lr] = b4.y;
            Bs[kk + 2][lr] = b4.z; Bs[kk + 3][lr] = b4.w;
        }
        __syncthreads();

#pragma unroll
        for (int kk = 0; kk < 16; kk++) {
            float a[8], b[8];
            *(float4*)&a[0] = *(const float4*)&As[kk][ty * 8 + 0];
            *(float4*)&a[4] = *(const float4*)&As[kk][ty * 8 + 4];
            *(float4*)&b[0] = *(const float4*)&Bs[kk][tx * 8 + 0];
            *(float4*)&b[4] = *(const float4*)&Bs[kk][tx * 8 + 4];
#pragma unroll
            for (int i = 0; i < 8; i++)
#pragma unroll
                for (int j = 0; j < 8; j++) acc[i][j] += a[i] * b[j];
        }
        __syncthreads();
    }

#pragma unroll
    for (int i = 0; i < 8; i++) {
        int m = m0 + ty * 8 + i;      // m = b*TLEN + t
        int b = m >> 11;
        int t = m & (TLEN - 1);
#pragma unroll
        for (int j = 0; j < 8; j++) {
            int n = n0 + tx * 8 + j;  // n = h*DHEAD + dh
            int h = n >> 6;
            int dh = n & 63;
            g_q[(((b * HN + h) * TLEN + t) * DHEAD) + dh] = acc[i][j];
        }
    }
}

// ---------------------------------------------------------------------------
// Kernel 2: causal flash attention + residual, split-D.
// Grid: (T/64, H, B). 128 threads; lane pair (2r,2r+1) owns query row r,
// each lane holds 32 of the 64 head dims. K/V 64x64 tiles in smem with a
// static per-block slot rotation so the two halves never bank-conflict.
// ---------------------------------------------------------------------------
__global__ __launch_bounds__(128) void attn_kernel(const float* __restrict__ x,
                                                   const float* __restrict__ k,
                                                   const float* __restrict__ v,
                                                   float* __restrict__ out) {
    __shared__ float4 Ks4[64 * 16];
    __shared__ float4 Vs4[64 * 16];

    const int tid = threadIdx.x;
    const int half = tid & 1;          // which 32-dim half
    const int row = tid >> 1;          // query row within tile (0..63)
    const int qtile = gridDim.x - 1 - blockIdx.x;   // heavy tiles first
    const int h = blockIdx.y;
    const int b = blockIdx.z;
    const int qr = qtile * 64 + row;

    const float scale = 0.03125f;      // 1/sqrt(1024)

    // Q half-row and O half-accumulator in registers (natural block order).
    float4 qv4[8], o4[8];
    {
        const float4* qp = (const float4*)(g_q + ((size_t)((b * HN + h) * TLEN) + qr) * DHEAD) + half * 8;
#pragma unroll
        for (int i = 0; i < 8; i++) qv4[i] = qp[i];
    }
#pragma unroll
    for (int i = 0; i < 8; i++) o4[i] = make_float4(0.f, 0.f, 0.f, 0.f);

    float mrow = -CUDART_INF_F;
    float lrow = 0.f;

    const float4* kbase = (const float4*)(k + (size_t)((b * HN + h) * TLEN) * DHEAD);
    const float4* vbase = (const float4*)(v + (size_t)((b * HN + h) * TLEN) * DHEAD);

    for (int kt = 0; kt <= qtile; kt++) {
        // Load 64x64 K/V tiles: 1024 float4 each / 128 threads = 8 each.
        // Apply slot rotation on the upper 8 dim-blocks: blk>=8 -> 8+((blk+1)&7).
        const float4* kg = kbase + (size_t)kt * 64 * 16;
        const float4* vg = vbase + (size_t)kt * 64 * 16;
#pragma unroll
        for (int i = 0; i < 8; i++) {
            int idx = tid + i * 128;          // 0..1023
            int r = idx >> 4;
            int blk = idx & 15;
            int slot = (blk & 8) + ((blk + (blk >> 3)) & 7);
            Ks4[r * 16 + slot] = kg[idx];
            Vs4[r * 16 + slot] = vg[idx];
        }
        __syncthreads();

        const bool diag = (kt == qtile);

#pragma unroll 1
        for (int chunk = 0; chunk < 4; chunk++) {
            const int jb = chunk * 16;
            if (diag && jb > row) break;     // fully masked (and all later chunks)

            float s[16];
#pragma unroll
            for (int j = 0; j < 16; j++) {
                const float4* kr = Ks4 + (jb + j) * 16;
                float ax = 0.f, ay = 0.f, az = 0.f, aw = 0.f;
#pragma unroll
                for (int i = 0; i < 8; i++) {
                    int slot = half * 8 + ((i + half) & 7);   // rotated, conflict-free
                    float4 k4 = kr[slot];
                    ax += qv4[i].x * k4.x;
                    ay += qv4[i].y * k4.y;
                    az += qv4[i].z * k4.z;
                    aw += qv4[i].w * k4.w;
                }
                s[j] = (ax + ay) + (az + aw);
            }
            // Combine the two halves' partial dots.
#pragma unroll
            for (int j = 0; j < 16; j++)
                s[j] += __shfl_xor_sync(0xffffffffu, s[j], 1);

            float tmax = -CUDART_INF_F;
#pragma unroll
            for (int j = 0; j < 16; j++) {
                float sv = s[j] * scale;
                if (diag && (jb + j > row)) sv = -CUDART_INF_F;
                s[j] = sv;
                tmax = fmaxf(tmax, sv);
            }

            const float mnew = fmaxf(mrow, tmax);   // finite: chunk has >=1 valid key
            const float corr = __expf(mrow - mnew); // first chunk: exp(-inf)=0
            lrow *= corr;
#pragma unroll
            for (int i = 0; i < 8; i++) {
                o4[i].x *= corr; o4[i].y *= corr;
                o4[i].z *= corr; o4[i].w *= corr;
            }

#pragma unroll
            for (int j = 0; j < 16; j++) {
                float p = __expf(s[j] - mnew);
                lrow += p;
                const float4* vr = Vs4 + (jb + j) * 16;
#pragma unroll
                for (int i = 0; i < 8; i++) {
                    int slot = half * 8 + ((i + half) & 7);
                    float4 v4 = vr[slot];
                    o4[i].x += p * v4.x;
                    o4[i].y += p * v4.y;
                    o4[i].z += p * v4.z;
                    o4[i].w += p * v4.w;
                }
            }
            mrow = mnew;
        }
        __syncthreads();
    }

    // Residual add + write this half-row: out[b, qr, h*64 + half*32 .. +32).
    const float inv = 1.f / lrow;
    const float4* xp = (const float4*)(x + (size_t)(b * TLEN + qr) * DMODEL + h * DHEAD) + half * 8;
    float4* op = (float4*)(out + (size_t)(b * TLEN + qr) * DMODEL + h * DHEAD) + half * 8;
#pragma unroll
    for (int i = 0; i < 8; i++) {
        float4 x4 = xp[i];
        float4 r;
        r.x = x4.x + o4[i].x * inv;
        r.y = x4.y + o4[i].y * inv;
        r.z = x4.z + o4[i].z * inv;
        r.w = x4.w + o4[i].w * inv;
        op[i] = r;
    }
}

extern "C" void kernel_launch(void* const* d_in, const int* in_sizes, int n_in,
                              void* d_out, int out_size) {
    const float* x  = (const float*)d_in[0];   // [B,T,D]
    const float* k  = (const float*)d_in[1];   // [B,H,T,DH]
    const float* v  = (const float*)d_in[2];   // [B,H,T,DH]
    const float* Wq = (const float*)d_in[3];   // [D,D]
    float* out = (float*)d_out;                // [B,T,D]

    dim3 g1(DMODEL / 128, (BSZ * TLEN) / 128); // (8, 32)
    qgemm_kernel<<<g1, 256>>>(x, Wq);

    dim3 g2(TLEN / 64, HN, BSZ);               // (32, 16, 2)
    attn_kernel<<<g2, 128>>>(x, k, v, out);
}

// round 3
// speedup vs baseline: 2.3918x; 1.0767x over previous
#include <cuda_runtime.h>
#include <math_constants.h>

#define BSZ 2
#define TLEN 2048
#define DMODEL 1024
#define HN 16
#define DHEAD 64

// Q scratch in [B, H, T, DH] layout (16 MB).
__device__ float g_q[BSZ * HN * TLEN * DHEAD];

// ---------------------------------------------------------------------------
// Kernel 1: Q projection GEMM.  q = x @ Wq^T, written as [B,H,T,DH].
// 128x128 tile, K-tile 16, 256 threads, 8x8 per thread, register prefetch.
// ---------------------------------------------------------------------------
__global__ __launch_bounds__(256) void qgemm_kernel(const float* __restrict__ x,
                                                    const float* __restrict__ Wq) {
    __shared__ float As[16][128];
    __shared__ float Bs[16][128];

    const int tid = threadIdx.x;
    const int tx = tid & 15;
    const int ty = tid >> 4;
    const int m0 = blockIdx.y * 128;
    const int n0 = blockIdx.x * 128;

    const int lr = tid >> 1;         // row within tile (0..127)
    const int lc = tid & 1;          // which 8-float half of the 16 K values

    float acc[8][8];
#pragma unroll
    for (int i = 0; i < 8; i++)
#pragma unroll
        for (int j = 0; j < 8; j++) acc[i][j] = 0.f;

    float4 pa[2], pb[2];
    // initial tile load + store
#pragma unroll
    for (int q = 0; q < 2; q++) {
        int kk = lc * 8 + q * 4;
        pa[q] = *(const float4*)(x  + (size_t)(m0 + lr) * DMODEL + kk);
        pb[q] = *(const float4*)(Wq + (size_t)(n0 + lr) * DMODEL + kk);
    }
#pragma unroll
    for (int q = 0; q < 2; q++) {
        int kk = lc * 8 + q * 4;
        As[kk + 0][lr] = pa[q].x; As[kk + 1][lr] = pa[q].y;
        As[kk + 2][lr] = pa[q].z; As[kk + 3][lr] = pa[q].w;
        Bs[kk + 0][lr] = pb[q].x; Bs[kk + 1][lr] = pb[q].y;
        Bs[kk + 2][lr] = pb[q].z; Bs[kk + 3][lr] = pb[q].w;
    }
    __syncthreads();

    for (int k0 = 0; k0 < DMODEL; k0 += 16) {
        const bool has_next = (k0 + 16) < DMODEL;
        if (has_next) {
#pragma unroll
            for (int q = 0; q < 2; q++) {
                int kk = k0 + 16 + lc * 8 + q * 4;
                pa[q] = *(const float4*)(x  + (size_t)(m0 + lr) * DMODEL + kk);
                pb[q] = *(const float4*)(Wq + (size_t)(n0 + lr) * DMODEL + kk);
            }
        }

#pragma unroll
        for (int kk = 0; kk < 16; kk++) {
            float a[8], b[8];
            *(float4*)&a[0] = *(const float4*)&As[kk][ty * 8 + 0];
            *(float4*)&a[4] = *(const float4*)&As[kk][ty * 8 + 4];
            *(float4*)&b[0] = *(const float4*)&Bs[kk][tx * 8 + 0];
            *(float4*)&b[4] = *(const float4*)&Bs[kk][tx * 8 + 4];
#pragma unroll
            for (int i = 0; i < 8; i++)
#pragma unroll
                for (int j = 0; j < 8; j++) acc[i][j] += a[i] * b[j];
        }

        if (has_next) {
            __syncthreads();
#pragma unroll
            for (int q = 0; q < 2; q++) {
                int kk = lc * 8 + q * 4;
                As[kk + 0][lr] = pa[q].x; As[kk + 1][lr] = pa[q].y;
                As[kk + 2][lr] = pa[q].z; As[kk + 3][lr] = pa[q].w;
                Bs[kk + 0][lr] = pb[q].x; Bs[kk + 1][lr] = pb[q].y;
                Bs[kk + 2][lr] = pb[q].z; Bs[kk + 3][lr] = pb[q].w;
            }
            __syncthreads();
        }
    }

#pragma unroll
    for (int i = 0; i < 8; i++) {
        int m = m0 + ty * 8 + i;      // m = b*TLEN + t
        int b = m >> 11;
        int t = m & (TLEN - 1);
#pragma unroll
        for (int j = 0; j < 8; j++) {
            int n = n0 + tx * 8 + j;  // n = h*DHEAD + dh
            int h = n >> 6;
            int dh = n & 63;
            g_q[(((b * HN + h) * TLEN + t) * DHEAD) + dh] = acc[i][j];
        }
    }
}

// ---------------------------------------------------------------------------
// Kernel 2: GEMM-tiled causal flash attention + residual.
// Block: 256 threads, q-tile 128 rows, key-tile 64.
// Each thread owns an 8x4 register tile of S (rows x keys) and of O (rows x dh).
// Q dim-major in smem (loaded once), K transposed per tile, P via padded smem.
// Row stats reduced over 16-lane half-warps via shfl.
// ---------------------------------------------------------------------------
#define QS_STRIDE 132
#define KS_STRIDE 68
#define PS_STRIDE 66
#define QS_OFF 0
#define KS_OFF (64 * QS_STRIDE)                 // 8448
#define VS_OFF (KS_OFF + 64 * KS_STRIDE)        // 12800
#define PS_OFF (VS_OFF + 64 * 64)               // 16896
#define ATTN_SMEM_FLOATS (PS_OFF + 128 * PS_STRIDE)   // 25344
#define ATTN_SMEM_BYTES (ATTN_SMEM_FLOATS * 4)        // 101376

__global__ __launch_bounds__(256) void attn_kernel(const float* __restrict__ x,
                                                   const float* __restrict__ k,
                                                   const float* __restrict__ v,
                                                   float* __restrict__ out) {
    extern __shared__ float sm[];
    float* Qs = sm + QS_OFF;   // [64 kk][132 rows]
    float* Ks = sm + KS_OFF;   // [64 kk][68 keys]
    float* Vs = sm + VS_OFF;   // [64 keys][64 dh]
    float* Ps = sm + PS_OFF;   // [128 rows][66 keys]

    const int tid = threadIdx.x;
    const int tx4 = (tid & 15) * 4;   // key group (QK) / dh group (AV)
    const int ty8 = (tid >> 4) * 8;   // row group
    const int qt = gridDim.x - 1 - blockIdx.x;   // heavy tiles first
    const int h = blockIdx.y;
    const int b = blockIdx.z;

    const float scale = 0.03125f;     // 1/sqrt(1024)

    // ---- load Q tile dim-major: Qs[kk][row] ----
    {
        const float4* qg = (const float4*)(g_q + ((size_t)((b * HN + h) * TLEN) + qt * 128) * DHEAD);
#pragma unroll
        for (int p = 0; p < 8; p++) {
            int idx = tid + p * 256;      // 0..2047
            int row = idx >> 4;
            int f = idx & 15;
            float4 q4 = qg[idx];
            Qs[(f * 4 + 0) * QS_STRIDE + row] = q4.x;
            Qs[(f * 4 + 1) * QS_STRIDE + row] = q4.y;
            Qs[(f * 4 + 2) * QS_STRIDE + row] = q4.z;
            Qs[(f * 4 + 3) * QS_STRIDE + row] = q4.w;
        }
    }

    float o[8][4];
    float mrow[8], lp[8];
#pragma unroll
    for (int i = 0; i < 8; i++) {
#pragma unroll
        for (int j = 0; j < 4; j++) o[i][j] = 0.f;
        mrow[i] = -CUDART_INF_F;
        lp[i] = 0.f;
    }

    const float4* kbase = (const float4*)(k + (size_t)((b * HN + h) * TLEN) * DHEAD);
    const float4* vbase = (const float4*)(v + (size_t)((b * HN + h) * TLEN) * DHEAD);

    const int nkt = 2 * qt + 2;
    for (int kt = 0; kt < nkt; kt++) {
        // ---- load K tile transposed (Ks[kk][key]) and V natural ----
#pragma unroll
        for (int p = 0; p < 4; p++) {
            int idx = tid + p * 256;      // 0..1023
            int key = idx >> 4;
            int f = idx & 15;
            float4 k4 = kbase[(size_t)(kt * 64 + key) * 16 + f];
            Ks[(f * 4 + 0) * KS_STRIDE + key] = k4.x;
            Ks[(f * 4 + 1) * KS_STRIDE + key] = k4.y;
            Ks[(f * 4 + 2) * KS_STRIDE + key] = k4.z;
            Ks[(f * 4 + 3) * KS_STRIDE + key] = k4.w;
            ((float4*)(Vs + key * 64))[f] = vbase[(size_t)(kt * 64 + key) * 16 + f];
        }
        __syncthreads();

        // ---- S = Q K^T (8x4 per thread) ----
        float s[8][4];
#pragma unroll
        for (int i = 0; i < 8; i++)
#pragma unroll
            for (int j = 0; j < 4; j++) s[i][j] = 0.f;

#pragma unroll 4
        for (int kk = 0; kk < 64; kk++) {
            float a[8], bb[4];
            *(float4*)&a[0] = *(const float4*)&Qs[kk * QS_STRIDE + ty8 + 0];
            *(float4*)&a[4] = *(const float4*)&Qs[kk * QS_STRIDE + ty8 + 4];
            *(float4*)&bb[0] = *(const float4*)&Ks[kk * KS_STRIDE + tx4];
#pragma unroll
            for (int i = 0; i < 8; i++)
#pragma unroll
                for (int j = 0; j < 4; j++) s[i][j] += a[i] * bb[j];
        }

        // ---- scale + mask + online softmax ----
        const bool needMask = (kt >= 2 * qt);
#pragma unroll
        for (int i = 0; i < 8; i++) {
            const int qrow = qt * 128 + ty8 + i;
            float tmax = -CUDART_INF_F;
#pragma unroll
            for (int j = 0; j < 4; j++) {
                float sv = s[i][j] * scale;
                if (needMask && (kt * 64 + tx4 + j > qrow)) sv = -CUDART_INF_F;
                s[i][j] = sv;
                tmax = fmaxf(tmax, sv);
            }
#pragma unroll
            for (int off = 1; off < 16; off <<= 1)
                tmax = fmaxf(tmax, __shfl_xor_sync(0xffffffffu, tmax, off));

            const float mnew = fmaxf(mrow[i], tmax);  // finite for every reachable row
            const float corr = __expf(mrow[i] - mnew);
            mrow[i] = mnew;
#pragma unroll
            for (int j = 0; j < 4; j++) o[i][j] *= corr;

            float psum = 0.f;
#pragma unroll
            for (int j = 0; j < 4; j++) {
                float p = __expf(s[i][j] - mnew);
                s[i][j] = p;
                psum += p;
            }
            lp[i] = lp[i] * corr + psum;

            // store P (scalar, 2-way max conflict)
#pragma unroll
            for (int j = 0; j < 4; j++)
                Ps[(ty8 + i) * PS_STRIDE + tx4 + j] = s[i][j];
        }
        __syncthreads();

        // ---- O += P V (8x4 per thread) ----
#pragma unroll 2
        for (int key = 0; key < 64; key++) {
            float bb[4];
            *(float4*)&bb[0] = *(const float4*)&Vs[key * 64 + tx4];
            float a[8];
#pragma unroll
            for (int i = 0; i < 8; i++) a[i] = Ps[(ty8 + i) * PS_STRIDE + key];
#pragma unroll
            for (int i = 0; i < 8; i++)
#pragma unroll
                for (int j = 0; j < 4; j++) o[i][j] += a[i] * bb[j];
        }
        __syncthreads();
    }

    // ---- epilogue: finish l reduction, normalize, residual add, store ----
#pragma unroll
    for (int i = 0; i < 8; i++) {
        float lsum = lp[i];
#pragma unroll
        for (int off = 1; off < 16; off <<= 1)
            lsum += __shfl_xor_sync(0xffffffffu, lsum, off);
        const float inv = 1.f / lsum;

        const int qrow = qt * 128 + ty8 + i;
        const float* xp = x + (size_t)(b * TLEN + qrow) * DMODEL + h * DHEAD + tx4;
        float* op = out + (size_t)(b * TLEN + qrow) * DMODEL + h * DHEAD + tx4;
        float4 x4 = *(const float4*)xp;
        float4 r;
        r.x = x4.x + o[i][0] * inv;
        r.y = x4.y + o[i][1] * inv;
        r.z = x4.z + o[i][2] * inv;
        r.w = x4.w + o[i][3] * inv;
        *(float4*)op = r;
    }
}

extern "C" void kernel_launch(void* const* d_in, const int* in_sizes, int n_in,
                              void* d_out, int out_size) {
    const float* x  = (const float*)d_in[0];   // [B,T,D]
    const float* k  = (const float*)d_in[1];   // [B,H,T,DH]
    const float* v  = (const float*)d_in[2];   // [B,H,T,DH]
    const float* Wq = (const float*)d_in[3];   // [D,D]
    float* out = (float*)d_out;                // [B,T,D]

    dim3 g1(DMODEL / 128, (BSZ * TLEN) / 128); // (8, 32)
    qgemm_kernel<<<g1, 256>>>(x, Wq);

    static int smem_set = 0;
    cudaFuncSetAttribute(attn_kernel, cudaFuncAttributeMaxDynamicSharedMemorySize,
                         ATTN_SMEM_BYTES);
    (void)smem_set;

    dim3 g2(TLEN / 128, HN, BSZ);              // (16, 16, 2)
    attn_kernel<<<g2, 256, ATTN_SMEM_BYTES>>>(x, k, v, out);
}

// round 4
// speedup vs baseline: 4.4683x; 1.8681x over previous
#include <cuda_runtime.h>
#include <math_constants.h>
#include <cstdint>

#define BSZ 2
#define TLEN 2048
#define DMODEL 1024
#define HN 16
#define DHEAD 64

// Q scratch in [B, H, T, DH] layout (16 MB).
__device__ float g_q[BSZ * HN * TLEN * DHEAD];

// ---------------------------------------------------------------------------
// Kernel 1: Q projection GEMM (fp32).  q = x @ Wq^T, written as [B,H,T,DH].
// 128x128 tile, K-tile 16, 256 threads, 8x8 per thread, register prefetch.
// ---------------------------------------------------------------------------
__global__ __launch_bounds__(256) void qgemm_kernel(const float* __restrict__ x,
                                                    const float* __restrict__ Wq) {
    __shared__ float As[16][128];
    __shared__ float Bs[16][128];

    const int tid = threadIdx.x;
    const int tx = tid & 15;
    const int ty = tid >> 4;
    const int m0 = blockIdx.y * 128;
    const int n0 = blockIdx.x * 128;

    const int lr = tid >> 1;
    const int lc = tid & 1;

    float acc[8][8];
#pragma unroll
    for (int i = 0; i < 8; i++)
#pragma unroll
        for (int j = 0; j < 8; j++) acc[i][j] = 0.f;

    float4 pa[2], pb[2];
#pragma unroll
    for (int q = 0; q < 2; q++) {
        int kk = lc * 8 + q * 4;
        pa[q] = *(const float4*)(x  + (size_t)(m0 + lr) * DMODEL + kk);
        pb[q] = *(const float4*)(Wq + (size_t)(n0 + lr) * DMODEL + kk);
    }
#pragma unroll
    for (int q = 0; q < 2; q++) {
        int kk = lc * 8 + q * 4;
        As[kk + 0][lr] = pa[q].x; As[kk + 1][lr] = pa[q].y;
        As[kk + 2][lr] = pa[q].z; As[kk + 3][lr] = pa[q].w;
        Bs[kk + 0][lr] = pb[q].x; Bs[kk + 1][lr] = pb[q].y;
        Bs[kk + 2][lr] = pb[q].z; Bs[kk + 3][lr] = pb[q].w;
    }
    __syncthreads();

    for (int k0 = 0; k0 < DMODEL; k0 += 16) {
        const bool has_next = (k0 + 16) < DMODEL;
        if (has_next) {
#pragma unroll
            for (int q = 0; q < 2; q++) {
                int kk = k0 + 16 + lc * 8 + q * 4;
                pa[q] = *(const float4*)(x  + (size_t)(m0 + lr) * DMODEL + kk);
                pb[q] = *(const float4*)(Wq + (size_t)(n0 + lr) * DMODEL + kk);
            }
        }

#pragma unroll
        for (int kk = 0; kk < 16; kk++) {
            float a[8], b[8];
            *(float4*)&a[0] = *(const float4*)&As[kk][ty * 8 + 0];
            *(float4*)&a[4] = *(const float4*)&As[kk][ty * 8 + 4];
            *(float4*)&b[0] = *(const float4*)&Bs[kk][tx * 8 + 0];
            *(float4*)&b[4] = *(const float4*)&Bs[kk][tx * 8 + 4];
#pragma unroll
            for (int i = 0; i < 8; i++)
#pragma unroll
                for (int j = 0; j < 8; j++) acc[i][j] += a[i] * b[j];
        }

        if (has_next) {
            __syncthreads();
#pragma unroll
            for (int q = 0; q < 2; q++) {
                int kk = lc * 8 + q * 4;
                As[kk + 0][lr] = pa[q].x; As[kk + 1][lr] = pa[q].y;
                As[kk + 2][lr] = pa[q].z; As[kk + 3][lr] = pa[q].w;
                Bs[kk + 0][lr] = pb[q].x; Bs[kk + 1][lr] = pb[q].y;
                Bs[kk + 2][lr] = pb[q].z; Bs[kk + 3][lr] = pb[q].w;
            }
            __syncthreads();
        }
    }

#pragma unroll
    for (int i = 0; i < 8; i++) {
        int m = m0 + ty * 8 + i;
        int b = m >> 11;
        int t = m & (TLEN - 1);
#pragma unroll
        for (int j = 0; j < 8; j++) {
            int n = n0 + tx * 8 + j;
            int h = n >> 6;
            int dh = n & 63;
            g_q[(((b * HN + h) * TLEN + t) * DHEAD) + dh] = acc[i][j];
        }
    }
}

// ---------------------------------------------------------------------------
// Kernel 2: tensor-core (HMMA tf32) causal flash attention + residual.
// 128 threads = 4 warps; warp w owns q-rows [qt*64 + 16w, +16).
// Q fragments in registers (whole kernel); K/V tf32 in smem (stride 68);
// S and O in mma accumulators; P converted C->A fragments via shuffles.
// ---------------------------------------------------------------------------
#define KSTRIDE 68

__device__ __forceinline__ uint32_t f2tf32(float f) {
    uint32_t u;
    asm("cvt.rna.tf32.f32 %0, %1;" : "=r"(u) : "f"(f));
    return u;
}

__device__ __forceinline__ void mma_tf32(float d[4], const uint32_t a[4],
                                         uint32_t b0, uint32_t b1) {
    asm volatile(
        "mma.sync.aligned.m16n8k8.row.col.f32.tf32.tf32.f32 "
        "{%0,%1,%2,%3}, {%4,%5,%6,%7}, {%8,%9}, {%0,%1,%2,%3};\n"
        : "+f"(d[0]), "+f"(d[1]), "+f"(d[2]), "+f"(d[3])
        : "r"(a[0]), "r"(a[1]), "r"(a[2]), "r"(a[3]), "r"(b0), "r"(b1));
}

__global__ __launch_bounds__(128) void attn_kernel(const float* __restrict__ x,
                                                   const float* __restrict__ k,
                                                   const float* __restrict__ v,
                                                   float* __restrict__ out) {
    __shared__ uint32_t Ks[64 * KSTRIDE];
    __shared__ uint32_t Vs[64 * KSTRIDE];

    const int tid = threadIdx.x;
    const int lane = tid & 31;
    const int wid = tid >> 5;
    const int qt = gridDim.x - 1 - blockIdx.x;   // heavy tiles first
    const int h = blockIdx.y;
    const int b = blockIdx.z;

    const int gid = lane >> 2;   // row-in-group (0..7)
    const int qid = lane & 3;    // col-in-group (0..3)

    const float scale = 0.03125f;   // 1/sqrt(1024)

    // ---- Q fragments (scaled, tf32), held in regs for whole kernel ----
    uint32_t qa[8][4];
    {
        const float* qb = g_q + ((size_t)((b * HN + h) * TLEN) + qt * 64 + wid * 16) * DHEAD;
#pragma unroll
        for (int s = 0; s < 8; s++) {
            qa[s][0] = f2tf32(qb[gid * 64 + 8 * s + qid] * scale);
            qa[s][1] = f2tf32(qb[(gid + 8) * 64 + 8 * s + qid] * scale);
            qa[s][2] = f2tf32(qb[gid * 64 + 8 * s + 4 + qid] * scale);
            qa[s][3] = f2tf32(qb[(gid + 8) * 64 + 8 * s + 4 + qid] * scale);
        }
    }

    float oacc[8][4];
#pragma unroll
    for (int n = 0; n < 8; n++)
#pragma unroll
        for (int j = 0; j < 4; j++) oacc[n][j] = 0.f;

    float m0 = -CUDART_INF_F, m1 = -CUDART_INF_F;
    float l0 = 0.f, l1 = 0.f;

    const float4* kg = (const float4*)(k + (size_t)((b * HN + h) * TLEN) * DHEAD);
    const float4* vg = (const float4*)(v + (size_t)((b * HN + h) * TLEN) * DHEAD);

    for (int kt = 0; kt <= qt; kt++) {
        __syncthreads();   // prior-iteration consumers done before overwrite
        // ---- load K/V tile, convert to tf32, store smem (stride 68) ----
#pragma unroll
        for (int p = 0; p < 8; p++) {
            int idx = tid + p * 128;        // 0..1023
            int key = idx >> 4;
            int f = idx & 15;
            float4 k4 = kg[(size_t)(kt * 64) * 16 + idx];
            float4 v4 = vg[(size_t)(kt * 64) * 16 + idx];
            uint4 ku, vu;
            ku.x = f2tf32(k4.x); ku.y = f2tf32(k4.y);
            ku.z = f2tf32(k4.z); ku.w = f2tf32(k4.w);
            vu.x = f2tf32(v4.x); vu.y = f2tf32(v4.y);
            vu.z = f2tf32(v4.z); vu.w = f2tf32(v4.w);
            *(uint4*)&Ks[key * KSTRIDE + 4 * f] = ku;
            *(uint4*)&Vs[key * KSTRIDE + 4 * f] = vu;
        }
        __syncthreads();

        // ---- S = Q K^T : 8 n-tiles x 8 k-steps of m16n8k8 ----
        float sacc[8][4];
#pragma unroll
        for (int n = 0; n < 8; n++)
#pragma unroll
            for (int j = 0; j < 4; j++) sacc[n][j] = 0.f;

#pragma unroll
        for (int s = 0; s < 8; s++) {
#pragma unroll
            for (int n = 0; n < 8; n++) {
                uint32_t b0 = Ks[(8 * n + gid) * KSTRIDE + 8 * s + qid];
                uint32_t b1 = Ks[(8 * n + gid) * KSTRIDE + 8 * s + 4 + qid];
                mma_tf32(sacc[n], qa[s], b0, b1);
            }
        }

        // ---- causal mask (diagonal tile only) ----
        if (kt == qt) {
            const int row0 = wid * 16 + gid;   // row offset == col offset base
            const int row1 = row0 + 8;
#pragma unroll
            for (int n = 0; n < 8; n++) {
                int c = 8 * n + 2 * qid;
                if (c > row0)     sacc[n][0] = -CUDART_INF_F;
                if (c + 1 > row0) sacc[n][1] = -CUDART_INF_F;
                if (c > row1)     sacc[n][2] = -CUDART_INF_F;
                if (c + 1 > row1) sacc[n][3] = -CUDART_INF_F;
            }
        }

        // ---- online softmax on fragments ----
        float tmax0 = -CUDART_INF_F, tmax1 = -CUDART_INF_F;
#pragma unroll
        for (int n = 0; n < 8; n++) {
            tmax0 = fmaxf(tmax0, fmaxf(sacc[n][0], sacc[n][1]));
            tmax1 = fmaxf(tmax1, fmaxf(sacc[n][2], sacc[n][3]));
        }
        tmax0 = fmaxf(tmax0, __shfl_xor_sync(0xffffffffu, tmax0, 1));
        tmax0 = fmaxf(tmax0, __shfl_xor_sync(0xffffffffu, tmax0, 2));
        tmax1 = fmaxf(tmax1, __shfl_xor_sync(0xffffffffu, tmax1, 1));
        tmax1 = fmaxf(tmax1, __shfl_xor_sync(0xffffffffu, tmax1, 2));

        const float mn0 = fmaxf(m0, tmax0);
        const float mn1 = fmaxf(m1, tmax1);
        const float corr0 = __expf(m0 - mn0);
        const float corr1 = __expf(m1 - mn1);
        m0 = mn0; m1 = mn1;

        float ps0 = 0.f, ps1 = 0.f;
#pragma unroll
        for (int n = 0; n < 8; n++) {
            float p0 = __expf(sacc[n][0] - mn0);
            float p1 = __expf(sacc[n][1] - mn0);
            float p2 = __expf(sacc[n][2] - mn1);
            float p3 = __expf(sacc[n][3] - mn1);
            sacc[n][0] = p0; sacc[n][1] = p1;
            sacc[n][2] = p2; sacc[n][3] = p3;
            ps0 += p0 + p1;
            ps1 += p2 + p3;
        }
        l0 = l0 * corr0 + ps0;
        l1 = l1 * corr1 + ps1;
#pragma unroll
        for (int n = 0; n < 8; n++) {
            oacc[n][0] *= corr0; oacc[n][1] *= corr0;
            oacc[n][2] *= corr1; oacc[n][3] *= corr1;
        }

        // ---- convert P to tf32 in place ----
        uint32_t (*pu)[4] = reinterpret_cast<uint32_t(*)[4]>(sacc);
#pragma unroll
        for (int n = 0; n < 8; n++)
#pragma unroll
            for (int j = 0; j < 4; j++) pu[n][j] = f2tf32(sacc[n][j]);

        // ---- O += P V : C-frag -> A-frag via shuffles, then 8x8 mma ----
        const int srcA = (lane & ~3) | (qid >> 1);
        const int srcB = srcA + 2;
        const bool odd = (lane & 1);
#pragma unroll
        for (int s = 0; s < 8; s++) {
            uint32_t v00 = __shfl_sync(0xffffffffu, pu[s][0], srcA);
            uint32_t v01 = __shfl_sync(0xffffffffu, pu[s][1], srcA);
            uint32_t v10 = __shfl_sync(0xffffffffu, pu[s][0], srcB);
            uint32_t v11 = __shfl_sync(0xffffffffu, pu[s][1], srcB);
            uint32_t w00 = __shfl_sync(0xffffffffu, pu[s][2], srcA);
            uint32_t w01 = __shfl_sync(0xffffffffu, pu[s][3], srcA);
            uint32_t w10 = __shfl_sync(0xffffffffu, pu[s][2], srcB);
            uint32_t w11 = __shfl_sync(0xffffffffu, pu[s][3], srcB);
            uint32_t pa[4];
            pa[0] = odd ? v01 : v00;
            pa[2] = odd ? v11 : v10;
            pa[1] = odd ? w01 : w00;
            pa[3] = odd ? w11 : w10;
#pragma unroll
            for (int nd = 0; nd < 8; nd++) {
                uint32_t b0 = Vs[(8 * s + qid) * KSTRIDE + 8 * nd + gid];
                uint32_t b1 = Vs[(8 * s + 4 + qid) * KSTRIDE + 8 * nd + gid];
                mma_tf32(oacc[nd], pa, b0, b1);
            }
        }
    }

    // ---- epilogue: finish l, normalize, residual add, store ----
    l0 += __shfl_xor_sync(0xffffffffu, l0, 1);
    l0 += __shfl_xor_sync(0xffffffffu, l0, 2);
    l1 += __shfl_xor_sync(0xffffffffu, l1, 1);
    l1 += __shfl_xor_sync(0xffffffffu, l1, 2);
    const float inv0 = 1.f / l0;
    const float inv1 = 1.f / l1;

    const int row0 = qt * 64 + wid * 16 + gid;
    const int row1 = row0 + 8;
    const size_t base0 = (size_t)(b * TLEN + row0) * DMODEL + h * DHEAD + 2 * qid;
    const size_t base1 = (size_t)(b * TLEN + row1) * DMODEL + h * DHEAD + 2 * qid;
#pragma unroll
    for (int nd = 0; nd < 8; nd++) {
        float2 x0 = *(const float2*)(x + base0 + 8 * nd);
        float2 x1 = *(const float2*)(x + base1 + 8 * nd);
        float2 r0, r1;
        r0.x = x0.x + oacc[nd][0] * inv0;
        r0.y = x0.y + oacc[nd][1] * inv0;
        r1.x = x1.x + oacc[nd][2] * inv1;
        r1.y = x1.y + oacc[nd][3] * inv1;
        *(float2*)(out + base0 + 8 * nd) = r0;
        *(float2*)(out + base1 + 8 * nd) = r1;
    }
}

extern "C" void kernel_launch(void* const* d_in, const int* in_sizes, int n_in,
                              void* d_out, int out_size) {
    const float* x  = (const float*)d_in[0];   // [B,T,D]
    const float* k  = (const float*)d_in[1];   // [B,H,T,DH]
    const float* v  = (const float*)d_in[2];   // [B,H,T,DH]
    const float* Wq = (const float*)d_in[3];   // [D,D]
    float* out = (float*)d_out;                // [B,T,D]

    dim3 g1(DMODEL / 128, (BSZ * TLEN) / 128); // (8, 32)
    qgemm_kernel<<<g1, 256>>>(x, Wq);

    dim3 g2(TLEN / 64, HN, BSZ);               // (32, 16, 2)
    attn_kernel<<<g2, 128>>>(x, k, v, out);
}

// round 5
// speedup vs baseline: 13.1445x; 2.9417x over previous
#include <cuda_runtime.h>
#include <math_constants.h>
#include <cstdint>

#define BSZ 2
#define TLEN 2048
#define DMODEL 1024
#define HN 16
#define DHEAD 64

// Q scratch: bf16 pairs, pre-scaled, [B,H,T,32 words]. 8.4 MB.
__device__ uint32_t g_q[BSZ * HN * TLEN * 32];
// K/V scratch: bf16, [B,H,T,DH] as 8 uint4 (16B chunks) per row. 8.4 MB each.
__device__ uint4 g_kb4[BSZ * HN * TLEN * 8];
__device__ uint4 g_vb4[BSZ * HN * TLEN * 8];

__device__ __forceinline__ uint32_t f2tf32(float f) {
    uint32_t u;
    asm("cvt.rna.tf32.f32 %0, %1;" : "=r"(u) : "f"(f));
    return u;
}
__device__ __forceinline__ uint32_t pkbf16(float hi, float lo) {
    uint32_t u;
    asm("cvt.rn.bf16x2.f32 %0, %1, %2;" : "=r"(u) : "f"(hi), "f"(lo));
    return u;
}
__device__ __forceinline__ void mma_tf32(float d[4], const uint32_t a[4],
                                         uint32_t b0, uint32_t b1) {
    asm volatile(
        "mma.sync.aligned.m16n8k8.row.col.f32.tf32.tf32.f32 "
        "{%0,%1,%2,%3}, {%4,%5,%6,%7}, {%8,%9}, {%0,%1,%2,%3};\n"
        : "+f"(d[0]), "+f"(d[1]), "+f"(d[2]), "+f"(d[3])
        : "r"(a[0]), "r"(a[1]), "r"(a[2]), "r"(a[3]), "r"(b0), "r"(b1));
}
__device__ __forceinline__ void mma_bf16(float d[4], const uint32_t a[4],
                                         uint32_t b0, uint32_t b1) {
    asm volatile(
        "mma.sync.aligned.m16n8k16.row.col.f32.bf16.bf16.f32 "
        "{%0,%1,%2,%3}, {%4,%5,%6,%7}, {%8,%9}, {%0,%1,%2,%3};\n"
        : "+f"(d[0]), "+f"(d[1]), "+f"(d[2]), "+f"(d[3])
        : "r"(a[0]), "r"(a[1]), "r"(a[2]), "r"(a[3]), "r"(b0), "r"(b1));
}
__device__ __forceinline__ void ldsm4(uint32_t& d0, uint32_t& d1, uint32_t& d2,
                                      uint32_t& d3, uint32_t addr) {
    asm volatile("ldmatrix.sync.aligned.m8n8.x4.shared.b16 {%0,%1,%2,%3}, [%4];"
                 : "=r"(d0), "=r"(d1), "=r"(d2), "=r"(d3) : "r"(addr));
}
__device__ __forceinline__ void ldsm4t(uint32_t& d0, uint32_t& d1, uint32_t& d2,
                                       uint32_t& d3, uint32_t addr) {
    asm volatile("ldmatrix.sync.aligned.m8n8.x4.trans.shared.b16 {%0,%1,%2,%3}, [%4];"
                 : "=r"(d0), "=r"(d1), "=r"(d2), "=r"(d3) : "r"(addr));
}
#define CP16(dst, src) \
    asm volatile("cp.async.cg.shared.global [%0], [%1], 16;" :: "r"(dst), "l"(src))

// ---------------------------------------------------------------------------
// Kernel 0: convert K,V fp32 -> bf16 scratch.
// ---------------------------------------------------------------------------
__global__ __launch_bounds__(256) void convert_kv(const float* __restrict__ k,
                                                  const float* __restrict__ v) {
    int i = blockIdx.x * 256 + threadIdx.x;   // one uint4 (8 bf16) per thread
    const float4* k4 = (const float4*)k;
    const float4* v4 = (const float4*)v;
    float4 a = k4[2 * i], c = k4[2 * i + 1];
    uint4 o;
    o.x = pkbf16(a.y, a.x); o.y = pkbf16(a.w, a.z);
    o.z = pkbf16(c.y, c.x); o.w = pkbf16(c.w, c.z);
    g_kb4[i] = o;
    a = v4[2 * i]; c = v4[2 * i + 1];
    o.x = pkbf16(a.y, a.x); o.y = pkbf16(a.w, a.z);
    o.z = pkbf16(c.y, c.x); o.w = pkbf16(c.w, c.z);
    g_vb4[i] = o;
}

// ---------------------------------------------------------------------------
// Kernel 1: Q projection GEMM on tf32 tensor cores.
// Block 128x128, 256 thr = 8 warps (2M x 4N), warp 64x32. K-tile 32.
// Output: q * (1/sqrt(D)) packed bf16x2 into g_q.
// ---------------------------------------------------------------------------
__global__ __launch_bounds__(256, 2) void qgemm_kernel(const float* __restrict__ x,
                                                       const float* __restrict__ Wq) {
    __shared__ uint32_t As[128 * 36];
    __shared__ uint32_t Bs[128 * 36];

    const int tid = threadIdx.x;
    const int lane = tid & 31;
    const int wid = tid >> 5;
    const int wm = wid >> 2;          // 0..1
    const int wn = wid & 3;           // 0..3
    const int gid = lane >> 2;
    const int qid = lane & 3;
    const int m0 = blockIdx.y * 128;
    const int n0 = blockIdx.x * 128;

    float acc[4][4][4];   // [mf][nf][c]
#pragma unroll
    for (int mf = 0; mf < 4; mf++)
#pragma unroll
        for (int nf = 0; nf < 4; nf++)
#pragma unroll
            for (int c = 0; c < 4; c++) acc[mf][nf][c] = 0.f;

    for (int k0 = 0; k0 < DMODEL; k0 += 32) {
        // fill: 1024 chunks per tensor, 4 per thread
#pragma unroll
        for (int p = 0; p < 4; p++) {
            int c = tid + p * 256;
            int m = c >> 3;
            int kc = c & 7;
            float4 a4 = *(const float4*)(x  + (size_t)(m0 + m) * DMODEL + k0 + kc * 4);
            float4 b4 = *(const float4*)(Wq + (size_t)(n0 + m) * DMODEL + k0 + kc * 4);
            uint4 au, bu;
            au.x = f2tf32(a4.x); au.y = f2tf32(a4.y);
            au.z = f2tf32(a4.z); au.w = f2tf32(a4.w);
            bu.x = f2tf32(b4.x); bu.y = f2tf32(b4.y);
            bu.z = f2tf32(b4.z); bu.w = f2tf32(b4.w);
            *(uint4*)&As[m * 36 + kc * 4] = au;
            *(uint4*)&Bs[m * 36 + kc * 4] = bu;
        }
        __syncthreads();

#pragma unroll
        for (int ks = 0; ks < 4; ks++) {
            uint32_t af[4][4], bf[4][2];
#pragma unroll
            for (int mf = 0; mf < 4; mf++) {
                int row = wm * 64 + mf * 16;
                af[mf][0] = As[(row + gid) * 36 + ks * 8 + qid];
                af[mf][1] = As[(row + gid + 8) * 36 + ks * 8 + qid];
                af[mf][2] = As[(row + gid) * 36 + ks * 8 + qid + 4];
                af[mf][3] = As[(row + gid + 8) * 36 + ks * 8 + qid + 4];
            }
#pragma unroll
            for (int nf = 0; nf < 4; nf++) {
                int col = wn * 32 + nf * 8;
                bf[nf][0] = Bs[(col + gid) * 36 + ks * 8 + qid];
                bf[nf][1] = Bs[(col + gid) * 36 + ks * 8 + qid + 4];
            }
#pragma unroll
            for (int mf = 0; mf < 4; mf++)
#pragma unroll
                for (int nf = 0; nf < 4; nf++)
                    mma_tf32(acc[mf][nf], af[mf], bf[nf][0], bf[nf][1]);
        }
        __syncthreads();
    }

    // epilogue: scale, pack bf16 pairs, store to g_q [b][h][t][pair]
    const float scale = 0.03125f;   // 1/sqrt(1024), exact power of 2
#pragma unroll
    for (int mf = 0; mf < 4; mf++) {
#pragma unroll
        for (int nf = 0; nf < 4; nf++) {
            int m = m0 + wm * 64 + mf * 16 + gid;
            int n = n0 + wn * 32 + nf * 8 + 2 * qid;
            int b = m >> 11;
            int t = m & (TLEN - 1);
            int h = n >> 6;
            int pair = (n & 63) >> 1;
            size_t a0 = ((size_t)(b * HN + h) * TLEN + t) * 32 + pair;
            g_q[a0]       = pkbf16(acc[mf][nf][1] * scale, acc[mf][nf][0] * scale);
            g_q[a0 + 256] = pkbf16(acc[mf][nf][3] * scale, acc[mf][nf][2] * scale);
        }
    }
}

// ---------------------------------------------------------------------------
// Kernel 2: bf16 tensor-core causal flash attention + residual.
// 128 thr = 4 warps; warp w owns q-rows [qt*64+16w, +16). kv-tile 64 keys.
// K/V bf16 tiles via cp.async double buffer, SW128-swizzled; ldmatrix frags.
// ---------------------------------------------------------------------------
__global__ __launch_bounds__(128, 4) void attn_kernel(const float* __restrict__ x,
                                                      float* __restrict__ out) {
    __shared__ uint32_t smbuf[2 * 2 * 2048];   // [stage][K/V][64*32 u32] = 32KB

    const int tid = threadIdx.x;
    const int lane = tid & 31;
    const int wid = tid >> 5;
    const int qt = gridDim.x - 1 - blockIdx.x;   // heavy tiles first
    const int h = blockIdx.y;
    const int b = blockIdx.z;

    const int gid = lane >> 2;
    const int qid = lane & 3;
    const int i7 = lane & 7;
    const int half = (lane >> 3) & 1;
    const int koct = lane >> 4;

    const unsigned smbase = (unsigned)__cvta_generic_to_shared(smbuf);

    // ---- Q fragments: bf16 pairs, pre-scaled, straight from g_q ----
    uint32_t qa[4][4];
    {
        const uint32_t* qg = g_q + ((size_t)((b * HN + h) * TLEN) + qt * 64 + wid * 16) * 32;
#pragma unroll
        for (int s = 0; s < 4; s++) {
            qa[s][0] = qg[gid * 32 + 8 * s + qid];
            qa[s][1] = qg[(gid + 8) * 32 + 8 * s + qid];
            qa[s][2] = qg[gid * 32 + 8 * s + qid + 4];
            qa[s][3] = qg[(gid + 8) * 32 + 8 * s + qid + 4];
        }
    }

    float oacc[8][4];
#pragma unroll
    for (int n = 0; n < 8; n++)
#pragma unroll
        for (int j = 0; j < 4; j++) oacc[n][j] = 0.f;

    float m0 = -CUDART_INF_F, m1 = -CUDART_INF_F;
    float l0 = 0.f, l1 = 0.f;

    const char* kgc = (const char*)(g_kb4 + (size_t)((b * HN + h) * TLEN) * 8);
    const char* vgc = (const char*)(g_vb4 + (size_t)((b * HN + h) * TLEN) * 8);

    // fill lambda: tile kt -> stage st
    auto fill = [&](int kt, int st) {
        const char* ks = kgc + (size_t)kt * 64 * 128;
        const char* vs = vgc + (size_t)kt * 64 * 128;
        unsigned kd = smbase + st * 16384;
        unsigned vd = kd + 8192;
#pragma unroll
        for (int i = 0; i < 4; i++) {
            int c = tid + i * 128;       // 0..511
            int key = c >> 3;
            int ch = c & 7;
            unsigned sw = (unsigned)((ch ^ (key & 7)) << 4);
            CP16(kd + key * 128 + sw, ks + key * 128 + ch * 16);
        }
#pragma unroll
        for (int i = 0; i < 4; i++) {
            int c = tid + i * 128;
            int key = c >> 3;
            int ch = c & 7;
            unsigned sw = (unsigned)((ch ^ (key & 7)) << 4);
            CP16(vd + key * 128 + sw, vs + key * 128 + ch * 16);
        }
        asm volatile("cp.async.commit_group;" ::: "memory");
    };

    fill(0, 0);

    for (int kt = 0; kt <= qt; kt++) {
        if (kt < qt) {
            fill(kt + 1, (kt + 1) & 1);
            asm volatile("cp.async.wait_group 1;" ::: "memory");
        } else {
            asm volatile("cp.async.wait_group 0;" ::: "memory");
        }
        __syncthreads();

        const unsigned kbuf = smbase + (kt & 1) * 16384;
        const unsigned vbuf = kbuf + 8192;

        // ---- S = Q K^T : 4 k-steps x 4 np (8 n-tiles) ----
        float sacc[8][4];
#pragma unroll
        for (int n = 0; n < 8; n++)
#pragma unroll
            for (int j = 0; j < 4; j++) sacc[n][j] = 0.f;

        const int key0 = 8 * koct + i7;
#pragma unroll
        for (int s = 0; s < 4; s++) {
#pragma unroll
            for (int np = 0; np < 4; np++) {
                uint32_t d0, d1, d2, d3;
                unsigned addr = kbuf + (unsigned)((16 * np + key0) * 128 +
                                                  (((2 * s + half) ^ i7) << 4));
                ldsm4(d0, d1, d2, d3, addr);
                mma_bf16(sacc[2 * np], qa[s], d0, d1);
                mma_bf16(sacc[2 * np + 1], qa[s], d2, d3);
            }
        }

        // ---- causal mask (diagonal tile only) ----
        if (kt == qt) {
            const int row0 = wid * 16 + gid;
            const int row1 = row0 + 8;
#pragma unroll
            for (int n = 0; n < 8; n++) {
                int c = 8 * n + 2 * qid;
                if (c > row0)     sacc[n][0] = -CUDART_INF_F;
                if (c + 1 > row0) sacc[n][1] = -CUDART_INF_F;
                if (c > row1)     sacc[n][2] = -CUDART_INF_F;
                if (c + 1 > row1) sacc[n][3] = -CUDART_INF_F;
            }
        }

        // ---- online softmax ----
        float t0 = -CUDART_INF_F, t1 = -CUDART_INF_F;
#pragma unroll
        for (int n = 0; n < 8; n++) {
            t0 = fmaxf(t0, fmaxf(sacc[n][0], sacc[n][1]));
            t1 = fmaxf(t1, fmaxf(sacc[n][2], sacc[n][3]));
        }
        t0 = fmaxf(t0, __shfl_xor_sync(0xffffffffu, t0, 1));
        t0 = fmaxf(t0, __shfl_xor_sync(0xffffffffu, t0, 2));
        t1 = fmaxf(t1, __shfl_xor_sync(0xffffffffu, t1, 1));
        t1 = fmaxf(t1, __shfl_xor_sync(0xffffffffu, t1, 2));

        const float mn0 = fmaxf(m0, t0);
        const float mn1 = fmaxf(m1, t1);
        const float corr0 = __expf(m0 - mn0);
        const float corr1 = __expf(m1 - mn1);
        m0 = mn0; m1 = mn1;

        float ps0 = 0.f, ps1 = 0.f;
#pragma unroll
        for (int n = 0; n < 8; n++) {
            float p0 = __expf(sacc[n][0] - mn0);
            float p1 = __expf(sacc[n][1] - mn0);
            float p2 = __expf(sacc[n][2] - mn1);
            float p3 = __expf(sacc[n][3] - mn1);
            sacc[n][0] = p0; sacc[n][1] = p1;
            sacc[n][2] = p2; sacc[n][3] = p3;
            ps0 += p0 + p1;
            ps1 += p2 + p3;
        }
        l0 = l0 * corr0 + ps0;
        l1 = l1 * corr1 + ps1;
#pragma unroll
        for (int n = 0; n < 8; n++) {
            oacc[n][0] *= corr0; oacc[n][1] *= corr0;
            oacc[n][2] *= corr1; oacc[n][3] *= corr1;
        }

        // ---- P: C-frag -> bf16 A-frags (pure register repack) ----
        uint32_t pu[4][4];
#pragma unroll
        for (int s = 0; s < 4; s++) {
            pu[s][0] = pkbf16(sacc[2 * s][1], sacc[2 * s][0]);
            pu[s][1] = pkbf16(sacc[2 * s][3], sacc[2 * s][2]);
            pu[s][2] = pkbf16(sacc[2 * s + 1][1], sacc[2 * s + 1][0]);
            pu[s][3] = pkbf16(sacc[2 * s + 1][3], sacc[2 * s + 1][2]);
        }

        // ---- O += P V : trans-ldmatrix on V ----
#pragma unroll
        for (int nd = 0; nd < 4; nd++) {
#pragma unroll
            for (int s = 0; s < 4; s++) {
                uint32_t d0, d1, d2, d3;
                int keyv = 16 * s + 8 * half + i7;
                unsigned addr = vbuf + (unsigned)(keyv * 128 +
                                                  (((2 * nd + koct) ^ i7) << 4));
                ldsm4t(d0, d1, d2, d3, addr);
                mma_bf16(oacc[2 * nd], pu[s], d0, d1);
                mma_bf16(oacc[2 * nd + 1], pu[s], d2, d3);
            }
        }
        __syncthreads();
    }

    // ---- epilogue ----
    l0 += __shfl_xor_sync(0xffffffffu, l0, 1);
    l0 += __shfl_xor_sync(0xffffffffu, l0, 2);
    l1 += __shfl_xor_sync(0xffffffffu, l1, 1);
    l1 += __shfl_xor_sync(0xffffffffu, l1, 2);
    const float inv0 = 1.f / l0;
    const float inv1 = 1.f / l1;

    const int row0 = qt * 64 + wid * 16 + gid;
    const int row1 = row0 + 8;
    const size_t base0 = (size_t)(b * TLEN + row0) * DMODEL + h * DHEAD + 2 * qid;
    const size_t base1 = (size_t)(b * TLEN + row1) * DMODEL + h * DHEAD + 2 * qid;
#pragma unroll
    for (int nd = 0; nd < 8; nd++) {
        float2 x0 = *(const float2*)(x + base0 + 8 * nd);
        float2 x1 = *(const float2*)(x + base1 + 8 * nd);
        float2 r0, r1;
        r0.x = x0.x + oacc[nd][0] * inv0;
        r0.y = x0.y + oacc[nd][1] * inv0;
        r1.x = x1.x + oacc[nd][2] * inv1;
        r1.y = x1.y + oacc[nd][3] * inv1;
        *(float2*)(out + base0 + 8 * nd) = r0;
        *(float2*)(out + base1 + 8 * nd) = r1;
    }
}

extern "C" void kernel_launch(void* const* d_in, const int* in_sizes, int n_in,
                              void* d_out, int out_size) {
    const float* x  = (const float*)d_in[0];   // [B,T,D]
    const float* k  = (const float*)d_in[1];   // [B,H,T,DH]
    const float* v  = (const float*)d_in[2];   // [B,H,T,DH]
    const float* Wq = (const float*)d_in[3];   // [D,D]
    float* out = (float*)d_out;                // [B,T,D]

    convert_kv<<<BSZ * HN * TLEN * 8 / 256, 256>>>(k, v);   // 2048 blocks

    dim3 g1(DMODEL / 128, (BSZ * TLEN) / 128); // (8, 32)
    qgemm_kernel<<<g1, 256>>>(x, Wq);

    dim3 g2(TLEN / 64, HN, BSZ);               // (32, 16, 2)
    attn_kernel<<<g2, 128>>>(x, out);
}

// round 6
// speedup vs baseline: 18.1534x; 1.3811x over previous
#include <cuda_runtime.h>
#include <math_constants.h>
#include <cstdint>

#define BSZ 2
#define TLEN 2048
#define DMODEL 1024
#define HN 16
#define DHEAD 64

// Q scratch: bf16 pairs, pre-scaled by log2(e)/sqrt(D), [B,H,T,32 words]. 8.4 MB.
__device__ uint32_t g_q[BSZ * HN * TLEN * 32];
// K/V/x/Wq bf16 scratch (16B chunks).
__device__ uint4 g_kb4[BSZ * HN * TLEN * 8];
__device__ uint4 g_vb4[BSZ * HN * TLEN * 8];
__device__ uint4 g_xb[BSZ * TLEN * DMODEL / 8];
__device__ uint4 g_wb[DMODEL * DMODEL / 8];

#define N4X (BSZ * TLEN * DMODEL / 8)   // 524288
#define N4W (DMODEL * DMODEL / 8)       // 131072

__device__ __forceinline__ uint32_t pkbf16(float hi, float lo) {
    uint32_t u;
    asm("cvt.rn.bf16x2.f32 %0, %1, %2;" : "=r"(u) : "f"(hi), "f"(lo));
    return u;
}
__device__ __forceinline__ void mma_bf16(float d[4], const uint32_t a[4],
                                         uint32_t b0, uint32_t b1) {
    asm volatile(
        "mma.sync.aligned.m16n8k16.row.col.f32.bf16.bf16.f32 "
        "{%0,%1,%2,%3}, {%4,%5,%6,%7}, {%8,%9}, {%0,%1,%2,%3};\n"
        : "+f"(d[0]), "+f"(d[1]), "+f"(d[2]), "+f"(d[3])
        : "r"(a[0]), "r"(a[1]), "r"(a[2]), "r"(a[3]), "r"(b0), "r"(b1));
}
__device__ __forceinline__ void ldsm4(uint32_t& d0, uint32_t& d1, uint32_t& d2,
                                      uint32_t& d3, uint32_t addr) {
    asm volatile("ldmatrix.sync.aligned.m8n8.x4.shared.b16 {%0,%1,%2,%3}, [%4];"
                 : "=r"(d0), "=r"(d1), "=r"(d2), "=r"(d3) : "r"(addr));
}
__device__ __forceinline__ void ldsm4t(uint32_t& d0, uint32_t& d1, uint32_t& d2,
                                       uint32_t& d3, uint32_t addr) {
    asm volatile("ldmatrix.sync.aligned.m8n8.x4.trans.shared.b16 {%0,%1,%2,%3}, [%4];"
                 : "=r"(d0), "=r"(d1), "=r"(d2), "=r"(d3) : "r"(addr));
}
#define CP16(dst, src) \
    asm volatile("cp.async.cg.shared.global [%0], [%1], 16;" :: "r"(dst), "l"(src))

// ---------------------------------------------------------------------------
// Kernel 0: convert x, k, v, Wq fp32 -> bf16 scratch. One uint4 per thread.
// ---------------------------------------------------------------------------
__global__ __launch_bounds__(256) void convert_all(const float* __restrict__ x,
                                                   const float* __restrict__ k,
                                                   const float* __restrict__ v,
                                                   const float* __restrict__ w) {
    int i = blockIdx.x * 256 + threadIdx.x;
    const float4* src;
    uint4* dst;
    if (i < N4X)            { src = (const float4*)x; dst = g_xb; }
    else if (i < 2 * N4X)   { src = (const float4*)k; dst = g_kb4; i -= N4X; }
    else if (i < 3 * N4X)   { src = (const float4*)v; dst = g_vb4; i -= 2 * N4X; }
    else                    { src = (const float4*)w; dst = g_wb;  i -= 3 * N4X;
                              if (i >= N4W) return; }
    float4 a = src[2 * i], c = src[2 * i + 1];
    uint4 o;
    o.x = pkbf16(a.y, a.x); o.y = pkbf16(a.w, a.z);
    o.z = pkbf16(c.y, c.x); o.w = pkbf16(c.w, c.z);
    dst[i] = o;
}

// ---------------------------------------------------------------------------
// Kernel 1: Q projection GEMM, bf16 tensor cores.
// Block 128x128, 256 thr = 8 warps (2M x 4N), warp 64x32. K-tile 64 (bf16),
// cp.async double buffer (64KB dyn smem), ldmatrix + mma m16n8k16.
// Output pre-scaled by log2(e)/sqrt(D), packed bf16x2 into g_q.
// ---------------------------------------------------------------------------
#define GEMM_SMEM 65536

__global__ __launch_bounds__(256, 2) void qgemm_kernel() {
    extern __shared__ uint8_t dynsm[];
    const unsigned smbase = (unsigned)__cvta_generic_to_shared(dynsm);

    const int tid = threadIdx.x;
    const int lane = tid & 31;
    const int wid = tid >> 5;
    const int wm = wid >> 2;          // 0..1
    const int wn = wid & 3;           // 0..3
    const int gid = lane >> 2;
    const int qid = lane & 3;
    const int m0 = blockIdx.y * 128;
    const int n0 = blockIdx.x * 128;

    const char* xg = (const char*)g_xb;   // rows of 2048 bytes
    const char* wg = (const char*)g_wb;

    auto fill = [&](int kt, int st) {
        unsigned sA = smbase + st * 32768;
        unsigned sB = sA + 16384;
#pragma unroll
        for (int p = 0; p < 4; p++) {
            int c = tid + p * 256;       // 0..1023
            int row = c >> 3;
            int ch = c & 7;
            unsigned sw = (unsigned)((ch ^ (row & 7)) << 4);
            CP16(sA + row * 128 + sw, xg + (size_t)(m0 + row) * 2048 + kt * 128 + ch * 16);
        }
#pragma unroll
        for (int p = 0; p < 4; p++) {
            int c = tid + p * 256;
            int row = c >> 3;
            int ch = c & 7;
            unsigned sw = (unsigned)((ch ^ (row & 7)) << 4);
            CP16(sB + row * 128 + sw, wg + (size_t)(n0 + row) * 2048 + kt * 128 + ch * 16);
        }
        asm volatile("cp.async.commit_group;" ::: "memory");
    };

    float acc[4][4][4];
#pragma unroll
    for (int mf = 0; mf < 4; mf++)
#pragma unroll
        for (int nf = 0; nf < 4; nf++)
#pragma unroll
            for (int c = 0; c < 4; c++) acc[mf][nf][c] = 0.f;

    fill(0, 0);

    const int ar = wm * 64 + (lane & 7) + 8 * ((lane >> 3) & 1);
    const int ach = lane >> 4;
    const int br = wn * 32 + 16 * (lane >> 4) + (lane & 7);
    const int bch = (lane >> 3) & 1;

    for (int kt = 0; kt < 16; kt++) {
        if (kt < 15) {
            fill(kt + 1, (kt + 1) & 1);
            asm volatile("cp.async.wait_group 1;" ::: "memory");
        } else {
            asm volatile("cp.async.wait_group 0;" ::: "memory");
        }
        __syncthreads();

        unsigned sA = smbase + (kt & 1) * 32768;
        unsigned sB = sA + 16384;

#pragma unroll
        for (int ks = 0; ks < 4; ks++) {
            uint32_t af[4][4];
#pragma unroll
            for (int mf = 0; mf < 4; mf++) {
                int row = ar + mf * 16;
                int ch = 2 * ks + ach;
                ldsm4(af[mf][0], af[mf][1], af[mf][2], af[mf][3],
                      sA + (unsigned)(row * 128 + ((ch ^ (row & 7)) << 4)));
            }
            uint32_t bf[4][2];
#pragma unroll
            for (int npair = 0; npair < 2; npair++) {
                int row = br;                       // lanes 16-31 already offset +16
                int rbase = wn * 32 + npair * 16 + 8 * 0;   // base group
                // address: rows (wn*32 + npair*16) + lane-pattern
                int r = wn * 32 + npair * 16 + 8 * (lane >> 4) + (lane & 7);
                int ch = 2 * ks + bch;
                uint32_t d0, d1, d2, d3;
                ldsm4(d0, d1, d2, d3,
                      sB + (unsigned)(r * 128 + ((ch ^ (r & 7)) << 4)));
                bf[2 * npair][0] = d0; bf[2 * npair][1] = d1;
                bf[2 * npair + 1][0] = d2; bf[2 * npair + 1][1] = d3;
                (void)row; (void)rbase;
            }
#pragma unroll
            for (int mf = 0; mf < 4; mf++)
#pragma unroll
                for (int nf = 0; nf < 4; nf++)
                    mma_bf16(acc[mf][nf], af[mf], bf[nf][0], bf[nf][1]);
        }
        __syncthreads();
    }

    // epilogue: scale by log2(e)/sqrt(D), pack bf16 pairs, store to g_q
    const float scale = 0.04508422f;   // log2(e)/32
#pragma unroll
    for (int mf = 0; mf < 4; mf++) {
#pragma unroll
        for (int nf = 0; nf < 4; nf++) {
            int m = m0 + wm * 64 + mf * 16 + gid;
            int n = n0 + wn * 32 + nf * 8 + 2 * qid;
            int b = m >> 11;
            int t = m & (TLEN - 1);
            int h = n >> 6;
            int pair = (n & 63) >> 1;
            size_t a0 = ((size_t)(b * HN + h) * TLEN + t) * 32 + pair;
            g_q[a0]       = pkbf16(acc[mf][nf][1] * scale, acc[mf][nf][0] * scale);
            g_q[a0 + 256] = pkbf16(acc[mf][nf][3] * scale, acc[mf][nf][2] * scale);
        }
    }
}

// ---------------------------------------------------------------------------
// Kernel 2: bf16 tensor-core causal flash attention + residual (exp2 softmax).
// ---------------------------------------------------------------------------
__global__ __launch_bounds__(128, 4) void attn_kernel(const float* __restrict__ x,
                                                      float* __restrict__ out) {
    __shared__ uint32_t smbuf[2 * 2 * 2048];   // [stage][K/V][64*32 u32] = 32KB

    const int tid = threadIdx.x;
    const int lane = tid & 31;
    const int wid = tid >> 5;
    const int qt = gridDim.x - 1 - blockIdx.x;   // heavy tiles first
    const int h = blockIdx.y;
    const int b = blockIdx.z;

    const int gid = lane >> 2;
    const int qid = lane & 3;
    const int i7 = lane & 7;
    const int half = (lane >> 3) & 1;
    const int koct = lane >> 4;

    const unsigned smbase = (unsigned)__cvta_generic_to_shared(smbuf);

    // ---- Q fragments: bf16 pairs, pre-scaled (incl. log2e), from g_q ----
    uint32_t qa[4][4];
    {
        const uint32_t* qg = g_q + ((size_t)((b * HN + h) * TLEN) + qt * 64 + wid * 16) * 32;
#pragma unroll
        for (int s = 0; s < 4; s++) {
            qa[s][0] = qg[gid * 32 + 8 * s + qid];
            qa[s][1] = qg[(gid + 8) * 32 + 8 * s + qid];
            qa[s][2] = qg[gid * 32 + 8 * s + qid + 4];
            qa[s][3] = qg[(gid + 8) * 32 + 8 * s + qid + 4];
        }
    }

    float oacc[8][4];
#pragma unroll
    for (int n = 0; n < 8; n++)
#pragma unroll
        for (int j = 0; j < 4; j++) oacc[n][j] = 0.f;

    float m0 = -CUDART_INF_F, m1 = -CUDART_INF_F;
    float l0 = 0.f, l1 = 0.f;

    const char* kgc = (const char*)(g_kb4 + (size_t)((b * HN + h) * TLEN) * 8);
    const char* vgc = (const char*)(g_vb4 + (size_t)((b * HN + h) * TLEN) * 8);

    auto fill = [&](int kt, int st) {
        const char* ks = kgc + (size_t)kt * 64 * 128;
        const char* vs = vgc + (size_t)kt * 64 * 128;
        unsigned kd = smbase + st * 16384;
        unsigned vd = kd + 8192;
#pragma unroll
        for (int i = 0; i < 4; i++) {
            int c = tid + i * 128;
            int key = c >> 3;
            int ch = c & 7;
            unsigned sw = (unsigned)((ch ^ (key & 7)) << 4);
            CP16(kd + key * 128 + sw, ks + key * 128 + ch * 16);
        }
#pragma unroll
        for (int i = 0; i < 4; i++) {
            int c = tid + i * 128;
            int key = c >> 3;
            int ch = c & 7;
            unsigned sw = (unsigned)((ch ^ (key & 7)) << 4);
            CP16(vd + key * 128 + sw, vs + key * 128 + ch * 16);
        }
        asm volatile("cp.async.commit_group;" ::: "memory");
    };

    fill(0, 0);

    for (int kt = 0; kt <= qt; kt++) {
        if (kt < qt) {
            fill(kt + 1, (kt + 1) & 1);
            asm volatile("cp.async.wait_group 1;" ::: "memory");
        } else {
            asm volatile("cp.async.wait_group 0;" ::: "memory");
        }
        __syncthreads();

        const unsigned kbuf = smbase + (kt & 1) * 16384;
        const unsigned vbuf = kbuf + 8192;

        // ---- S = Q K^T ----
        float sacc[8][4];
#pragma unroll
        for (int n = 0; n < 8; n++)
#pragma unroll
            for (int j = 0; j < 4; j++) sacc[n][j] = 0.f;

        const int key0 = 8 * koct + i7;
#pragma unroll
        for (int s = 0; s < 4; s++) {
#pragma unroll
            for (int np = 0; np < 4; np++) {
                uint32_t d0, d1, d2, d3;
                unsigned addr = kbuf + (unsigned)((16 * np + key0) * 128 +
                                                  (((2 * s + half) ^ i7) << 4));
                ldsm4(d0, d1, d2, d3, addr);
                mma_bf16(sacc[2 * np], qa[s], d0, d1);
                mma_bf16(sacc[2 * np + 1], qa[s], d2, d3);
            }
        }

        // ---- causal mask (diagonal tile only) ----
        if (kt == qt) {
            const int row0 = wid * 16 + gid;
            const int row1 = row0 + 8;
#pragma unroll
            for (int n = 0; n < 8; n++) {
                int c = 8 * n + 2 * qid;
                if (c > row0)     sacc[n][0] = -CUDART_INF_F;
                if (c + 1 > row0) sacc[n][1] = -CUDART_INF_F;
                if (c > row1)     sacc[n][2] = -CUDART_INF_F;
                if (c + 1 > row1) sacc[n][3] = -CUDART_INF_F;
            }
        }

        // ---- online softmax (base-2: q pre-scaled by log2e) ----
        float t0 = -CUDART_INF_F, t1 = -CUDART_INF_F;
#pragma unroll
        for (int n = 0; n < 8; n++) {
            t0 = fmaxf(t0, fmaxf(sacc[n][0], sacc[n][1]));
            t1 = fmaxf(t1, fmaxf(sacc[n][2], sacc[n][3]));
        }
        t0 = fmaxf(t0, __shfl_xor_sync(0xffffffffu, t0, 1));
        t0 = fmaxf(t0, __shfl_xor_sync(0xffffffffu, t0, 2));
        t1 = fmaxf(t1, __shfl_xor_sync(0xffffffffu, t1, 1));
        t1 = fmaxf(t1, __shfl_xor_sync(0xffffffffu, t1, 2));

        const float mn0 = fmaxf(m0, t0);
        const float mn1 = fmaxf(m1, t1);
        const float corr0 = exp2f(m0 - mn0);
        const float corr1 = exp2f(m1 - mn1);
        m0 = mn0; m1 = mn1;

        float ps0 = 0.f, ps1 = 0.f;
#pragma unroll
        for (int n = 0; n < 8; n++) {
            float p0 = exp2f(sacc[n][0] - mn0);
            float p1 = exp2f(sacc[n][1] - mn0);
            float p2 = exp2f(sacc[n][2] - mn1);
            float p3 = exp2f(sacc[n][3] - mn1);
            sacc[n][0] = p0; sacc[n][1] = p1;
            sacc[n][2] = p2; sacc[n][3] = p3;
            ps0 += p0 + p1;
            ps1 += p2 + p3;
        }
        l0 = l0 * corr0 + ps0;
        l1 = l1 * corr1 + ps1;
#pragma unroll
        for (int n = 0; n < 8; n++) {
            oacc[n][0] *= corr0; oacc[n][1] *= corr0;
            oacc[n][2] *= corr1; oacc[n][3] *= corr1;
        }

        // ---- P: C-frag -> bf16 A-frags (register repack) ----
        uint32_t pu[4][4];
#pragma unroll
        for (int s = 0; s < 4; s++) {
            pu[s][0] = pkbf16(sacc[2 * s][1], sacc[2 * s][0]);
            pu[s][1] = pkbf16(sacc[2 * s][3], sacc[2 * s][2]);
            pu[s][2] = pkbf16(sacc[2 * s + 1][1], sacc[2 * s + 1][0]);
            pu[s][3] = pkbf16(sacc[2 * s + 1][3], sacc[2 * s + 1][2]);
        }

        // ---- O += P V ----
#pragma unroll
        for (int nd = 0; nd < 4; nd++) {
#pragma unroll
            for (int s = 0; s < 4; s++) {
                uint32_t d0, d1, d2, d3;
                int keyv = 16 * s + 8 * half + i7;
                unsigned addr = vbuf + (unsigned)(keyv * 128 +
                                                  (((2 * nd + koct) ^ i7) << 4));
                ldsm4t(d0, d1, d2, d3, addr);
                mma_bf16(oacc[2 * nd], pu[s], d0, d1);
                mma_bf16(oacc[2 * nd + 1], pu[s], d2, d3);
            }
        }
        __syncthreads();
    }

    // ---- epilogue ----
    l0 += __shfl_xor_sync(0xffffffffu, l0, 1);
    l0 += __shfl_xor_sync(0xffffffffu, l0, 2);
    l1 += __shfl_xor_sync(0xffffffffu, l1, 1);
    l1 += __shfl_xor_sync(0xffffffffu, l1, 2);
    const float inv0 = 1.f / l0;
    const float inv1 = 1.f / l1;

    const int row0 = qt * 64 + wid * 16 + gid;
    const int row1 = row0 + 8;
    const size_t base0 = (size_t)(b * TLEN + row0) * DMODEL + h * DHEAD + 2 * qid;
    const size_t base1 = (size_t)(b * TLEN + row1) * DMODEL + h * DHEAD + 2 * qid;
#pragma unroll
    for (int nd = 0; nd < 8; nd++) {
        float2 x0 = *(const float2*)(x + base0 + 8 * nd);
        float2 x1 = *(const float2*)(x + base1 + 8 * nd);
        float2 r0, r1;
        r0.x = x0.x + oacc[nd][0] * inv0;
        r0.y = x0.y + oacc[nd][1] * inv0;
        r1.x = x1.x + oacc[nd][2] * inv1;
        r1.y = x1.y + oacc[nd][3] * inv1;
        *(float2*)(out + base0 + 8 * nd) = r0;
        *(float2*)(out + base1 + 8 * nd) = r1;
    }
}

extern "C" void kernel_launch(void* const* d_in, const int* in_sizes, int n_in,
                              void* d_out, int out_size) {
    const float* x  = (const float*)d_in[0];   // [B,T,D]
    const float* k  = (const float*)d_in[1];   // [B,H,T,DH]
    const float* v  = (const float*)d_in[2];   // [B,H,T,DH]
    const float* Wq = (const float*)d_in[3];   // [D,D]
    float* out = (float*)d_out;                // [B,T,D]

    convert_all<<<(3 * N4X + N4W) / 256, 256>>>(x, k, v, Wq);   // 6656 blocks

    cudaFuncSetAttribute(qgemm_kernel, cudaFuncAttributeMaxDynamicSharedMemorySize,
                         GEMM_SMEM);
    dim3 g1(DMODEL / 128, (BSZ * TLEN) / 128); // (8, 32)
    qgemm_kernel<<<g1, 256, GEMM_SMEM>>>();

    dim3 g2(TLEN / 64, HN, BSZ);               // (32, 16, 2)
    attn_kernel<<<g2, 128>>>(x, out);
}

// round 7
// speedup vs baseline: 19.5027x; 1.0743x over previous
#include <cuda_runtime.h>
#include <math_constants.h>
#include <cstdint>

#define BSZ 2
#define TLEN 2048
#define DMODEL 1024
#define HN 16
#define DHEAD 64

// Q scratch: bf16 pairs, pre-scaled by log2(e)/sqrt(D), [B,H,T,32 words]. 8.4 MB.
__device__ uint32_t g_q[BSZ * HN * TLEN * 32];
// K bf16, V fp16, x/Wq bf16 scratch (16B chunks).
__device__ uint4 g_kb4[BSZ * HN * TLEN * 8];
__device__ uint4 g_vb4[BSZ * HN * TLEN * 8];
__device__ uint4 g_xb[BSZ * TLEN * DMODEL / 8];
__device__ uint4 g_wb[DMODEL * DMODEL / 8];

#define N4X (BSZ * TLEN * DMODEL / 8)   // 524288
#define N4W (DMODEL * DMODEL / 8)       // 131072

__device__ __forceinline__ uint32_t pkbf16(float hi, float lo) {
    uint32_t u;
    asm("cvt.rn.bf16x2.f32 %0, %1, %2;" : "=r"(u) : "f"(hi), "f"(lo));
    return u;
}
__device__ __forceinline__ uint32_t pkf16(float hi, float lo) {
    uint32_t u;
    asm("cvt.rn.f16x2.f32 %0, %1, %2;" : "=r"(u) : "f"(hi), "f"(lo));
    return u;
}
// exp2 of two floats -> packed f16x2 (one MUFU for two exps)
__device__ __forceinline__ uint32_t ex2_f16x2(float hi, float lo) {
    uint32_t u;
    asm("{.reg .b32 t;\n\t"
        "cvt.rn.f16x2.f32 t, %1, %2;\n\t"
        "ex2.approx.f16x2 %0, t;}"
        : "=r"(u) : "f"(hi), "f"(lo));
    return u;
}
__device__ __forceinline__ float ex2f(float x) {
    float y;
    asm("ex2.approx.f32 %0, %1;" : "=f"(y) : "f"(x));
    return y;
}
__device__ __forceinline__ void mma_bf16(float d[4], const uint32_t a[4],
                                         uint32_t b0, uint32_t b1) {
    asm volatile(
        "mma.sync.aligned.m16n8k16.row.col.f32.bf16.bf16.f32 "
        "{%0,%1,%2,%3}, {%4,%5,%6,%7}, {%8,%9}, {%0,%1,%2,%3};\n"
        : "+f"(d[0]), "+f"(d[1]), "+f"(d[2]), "+f"(d[3])
        : "r"(a[0]), "r"(a[1]), "r"(a[2]), "r"(a[3]), "r"(b0), "r"(b1));
}
__device__ __forceinline__ void mma_f16(float d[4], const uint32_t a[4],
                                        uint32_t b0, uint32_t b1) {
    asm volatile(
        "mma.sync.aligned.m16n8k16.row.col.f32.f16.f16.f32 "
        "{%0,%1,%2,%3}, {%4,%5,%6,%7}, {%8,%9}, {%0,%1,%2,%3};\n"
        : "+f"(d[0]), "+f"(d[1]), "+f"(d[2]), "+f"(d[3])
        : "r"(a[0]), "r"(a[1]), "r"(a[2]), "r"(a[3]), "r"(b0), "r"(b1));
}
__device__ __forceinline__ void ldsm4(uint32_t& d0, uint32_t& d1, uint32_t& d2,
                                      uint32_t& d3, uint32_t addr) {
    asm volatile("ldmatrix.sync.aligned.m8n8.x4.shared.b16 {%0,%1,%2,%3}, [%4];"
                 : "=r"(d0), "=r"(d1), "=r"(d2), "=r"(d3) : "r"(addr));
}
__device__ __forceinline__ void ldsm4t(uint32_t& d0, uint32_t& d1, uint32_t& d2,
                                       uint32_t& d3, uint32_t addr) {
    asm volatile("ldmatrix.sync.aligned.m8n8.x4.trans.shared.b16 {%0,%1,%2,%3}, [%4];"
                 : "=r"(d0), "=r"(d1), "=r"(d2), "=r"(d3) : "r"(addr));
}
#define CP16(dst, src) \
    asm volatile("cp.async.cg.shared.global [%0], [%1], 16;" :: "r"(dst), "l"(src))

// ---------------------------------------------------------------------------
// Kernel 0: convert x,k,Wq -> bf16 and v -> fp16 scratch. One uint4 per thread.
// ---------------------------------------------------------------------------
__global__ __launch_bounds__(256) void convert_all(const float* __restrict__ x,
                                                   const float* __restrict__ k,
                                                   const float* __restrict__ v,
                                                   const float* __restrict__ w) {
    int i = blockIdx.x * 256 + threadIdx.x;
    const float4* src;
    uint4* dst;
    int isv = 0;
    if (i < N4X)            { src = (const float4*)x; dst = g_xb; }
    else if (i < 2 * N4X)   { src = (const float4*)k; dst = g_kb4; i -= N4X; }
    else if (i < 3 * N4X)   { src = (const float4*)v; dst = g_vb4; i -= 2 * N4X; isv = 1; }
    else                    { src = (const float4*)w; dst = g_wb;  i -= 3 * N4X;
                              if (i >= N4W) return; }
    float4 a = src[2 * i], c = src[2 * i + 1];
    uint4 o;
    if (isv) {
        o.x = pkf16(a.y, a.x); o.y = pkf16(a.w, a.z);
        o.z = pkf16(c.y, c.x); o.w = pkf16(c.w, c.z);
    } else {
        o.x = pkbf16(a.y, a.x); o.y = pkbf16(a.w, a.z);
        o.z = pkbf16(c.y, c.x); o.w = pkbf16(c.w, c.z);
    }
    dst[i] = o;
}

// ---------------------------------------------------------------------------
// Kernel 1: Q projection GEMM, bf16 tensor cores.
// Block 128x128, 256 thr = 8 warps (2M x 4N), warp 64x32. K-tile 64 (bf16),
// cp.async double buffer, ldmatrix + mma m16n8k16.
// Output pre-scaled by log2(e)/sqrt(D), packed bf16x2 into g_q.
// ---------------------------------------------------------------------------
#define GEMM_SMEM 65536

__global__ __launch_bounds__(256, 2) void qgemm_kernel() {
    extern __shared__ uint8_t dynsm[];
    const unsigned smbase = (unsigned)__cvta_generic_to_shared(dynsm);

    const int tid = threadIdx.x;
    const int lane = tid & 31;
    const int wid = tid >> 5;
    const int wm = wid >> 2;
    const int wn = wid & 3;
    const int gid = lane >> 2;
    const int qid = lane & 3;
    const int m0 = blockIdx.y * 128;
    const int n0 = blockIdx.x * 128;

    const char* xg = (const char*)g_xb;   // rows of 2048 bytes
    const char* wg = (const char*)g_wb;

    auto fill = [&](int kt, int st) {
        unsigned sA = smbase + st * 32768;
        unsigned sB = sA + 16384;
#pragma unroll
        for (int p = 0; p < 4; p++) {
            int c = tid + p * 256;
            int row = c >> 3;
            int ch = c & 7;
            unsigned sw = (unsigned)((ch ^ (row & 7)) << 4);
            CP16(sA + row * 128 + sw, xg + (size_t)(m0 + row) * 2048 + kt * 128 + ch * 16);
        }
#pragma unroll
        for (int p = 0; p < 4; p++) {
            int c = tid + p * 256;
            int row = c >> 3;
            int ch = c & 7;
            unsigned sw = (unsigned)((ch ^ (row & 7)) << 4);
            CP16(sB + row * 128 + sw, wg + (size_t)(n0 + row) * 2048 + kt * 128 + ch * 16);
        }
        asm volatile("cp.async.commit_group;" ::: "memory");
    };

    float acc[4][4][4];
#pragma unroll
    for (int mf = 0; mf < 4; mf++)
#pragma unroll
        for (int nf = 0; nf < 4; nf++)
#pragma unroll
            for (int c = 0; c < 4; c++) acc[mf][nf][c] = 0.f;

    fill(0, 0);

    const int ar = wm * 64 + (lane & 7) + 8 * ((lane >> 3) & 1);
    const int ach = lane >> 4;
    const int bch = (lane >> 3) & 1;

    for (int kt = 0; kt < 16; kt++) {
        if (kt < 15) {
            fill(kt + 1, (kt + 1) & 1);
            asm volatile("cp.async.wait_group 1;" ::: "memory");
        } else {
            asm volatile("cp.async.wait_group 0;" ::: "memory");
        }
        __syncthreads();

        unsigned sA = smbase + (kt & 1) * 32768;
        unsigned sB = sA + 16384;

#pragma unroll
        for (int ks = 0; ks < 4; ks++) {
            uint32_t af[4][4];
#pragma unroll
            for (int mf = 0; mf < 4; mf++) {
                int row = ar + mf * 16;
                int ch = 2 * ks + ach;
                ldsm4(af[mf][0], af[mf][1], af[mf][2], af[mf][3],
                      sA + (unsigned)(row * 128 + ((ch ^ (row & 7)) << 4)));
            }
            uint32_t bf[4][2];
#pragma unroll
            for (int npair = 0; npair < 2; npair++) {
                int r = wn * 32 + npair * 16 + 8 * (lane >> 4) + (lane & 7);
                int ch = 2 * ks + bch;
                uint32_t d0, d1, d2, d3;
                ldsm4(d0, d1, d2, d3,
                      sB + (unsigned)(r * 128 + ((ch ^ (r & 7)) << 4)));
                bf[2 * npair][0] = d0; bf[2 * npair][1] = d1;
                bf[2 * npair + 1][0] = d2; bf[2 * npair + 1][1] = d3;
            }
#pragma unroll
            for (int mf = 0; mf < 4; mf++)
#pragma unroll
                for (int nf = 0; nf < 4; nf++)
                    mma_bf16(acc[mf][nf], af[mf], bf[nf][0], bf[nf][1]);
        }
        __syncthreads();
    }

    const float scale = 0.04508422f;   // log2(e)/32
#pragma unroll
    for (int mf = 0; mf < 4; mf++) {
#pragma unroll
        for (int nf = 0; nf < 4; nf++) {
            int m = m0 + wm * 64 + mf * 16 + gid;
            int n = n0 + wn * 32 + nf * 8 + 2 * qid;
            int b = m >> 11;
            int t = m & (TLEN - 1);
            int h = n >> 6;
            int pair = (n & 63) >> 1;
            size_t a0 = ((size_t)(b * HN + h) * TLEN + t) * 32 + pair;
            g_q[a0]       = pkbf16(acc[mf][nf][1] * scale, acc[mf][nf][0] * scale);
            g_q[a0 + 256] = pkbf16(acc[mf][nf][3] * scale, acc[mf][nf][2] * scale);
        }
    }
}

// ---------------------------------------------------------------------------
// Kernel 2: tensor-core causal flash attention + residual.
// QK in bf16 HMMA, softmax via ex2.approx.f16x2 (2 exps/MUFU, output = fp16
// A-fragment directly), AV in f16 HMMA, row-sum l via ones-column MMA.
// ---------------------------------------------------------------------------
__global__ __launch_bounds__(128, 4) void attn_kernel(const float* __restrict__ x,
                                                      float* __restrict__ out) {
    __shared__ uint32_t smbuf[2 * 2 * 2048];   // [stage][K/V][64*32 u32] = 32KB

    const int tid = threadIdx.x;
    const int lane = tid & 31;
    const int wid = tid >> 5;
    const int qt = gridDim.x - 1 - blockIdx.x;   // heavy tiles first
    const int h = blockIdx.y;
    const int b = blockIdx.z;

    const int gid = lane >> 2;
    const int qid = lane & 3;
    const int i7 = lane & 7;
    const int half = (lane >> 3) & 1;
    const int koct = lane >> 4;

    const uint32_t ONE2 = 0x3C003C00u;   // f16x2 {1.0, 1.0}

    const unsigned smbase = (unsigned)__cvta_generic_to_shared(smbuf);

    // ---- Q fragments: bf16 pairs, pre-scaled (incl. log2e), from g_q ----
    uint32_t qa[4][4];
    {
        const uint32_t* qg = g_q + ((size_t)((b * HN + h) * TLEN) + qt * 64 + wid * 16) * 32;
#pragma unroll
        for (int s = 0; s < 4; s++) {
            qa[s][0] = qg[gid * 32 + 8 * s + qid];
            qa[s][1] = qg[(gid + 8) * 32 + 8 * s + qid];
            qa[s][2] = qg[gid * 32 + 8 * s + qid + 4];
            qa[s][3] = qg[(gid + 8) * 32 + 8 * s + qid + 4];
        }
    }

    float oacc[8][4];
#pragma unroll
    for (int n = 0; n < 8; n++)
#pragma unroll
        for (int j = 0; j < 4; j++) oacc[n][j] = 0.f;
    float lacc[4] = {0.f, 0.f, 0.f, 0.f};   // ones-column row sums

    float m0 = -CUDART_INF_F, m1 = -CUDART_INF_F;

    const char* kgc = (const char*)(g_kb4 + (size_t)((b * HN + h) * TLEN) * 8);
    const char* vgc = (const char*)(g_vb4 + (size_t)((b * HN + h) * TLEN) * 8);

    auto fill = [&](int kt, int st) {
        const char* ks = kgc + (size_t)kt * 64 * 128;
        const char* vs = vgc + (size_t)kt * 64 * 128;
        unsigned kd = smbase + st * 16384;
        unsigned vd = kd + 8192;
#pragma unroll
        for (int i = 0; i < 4; i++) {
            int c = tid + i * 128;
            int key = c >> 3;
            int ch = c & 7;
            unsigned sw = (unsigned)((ch ^ (key & 7)) << 4);
            CP16(kd + key * 128 + sw, ks + key * 128 + ch * 16);
        }
#pragma unroll
        for (int i = 0; i < 4; i++) {
            int c = tid + i * 128;
            int key = c >> 3;
            int ch = c & 7;
            unsigned sw = (unsigned)((ch ^ (key & 7)) << 4);
            CP16(vd + key * 128 + sw, vs + key * 128 + ch * 16);
        }
        asm volatile("cp.async.commit_group;" ::: "memory");
    };

    fill(0, 0);

    for (int kt = 0; kt <= qt; kt++) {
        if (kt < qt) {
            fill(kt + 1, (kt + 1) & 1);
            asm volatile("cp.async.wait_group 1;" ::: "memory");
        } else {
            asm volatile("cp.async.wait_group 0;" ::: "memory");
        }
        __syncthreads();

        const unsigned kbuf = smbase + (kt & 1) * 16384;
        const unsigned vbuf = kbuf + 8192;

        // ---- S = Q K^T (bf16) ----
        float sacc[8][4];
#pragma unroll
        for (int n = 0; n < 8; n++)
#pragma unroll
            for (int j = 0; j < 4; j++) sacc[n][j] = 0.f;

        const int key0 = 8 * koct + i7;
#pragma unroll
        for (int s = 0; s < 4; s++) {
#pragma unroll
            for (int np = 0; np < 4; np++) {
                uint32_t d0, d1, d2, d3;
                unsigned addr = kbuf + (unsigned)((16 * np + key0) * 128 +
                                                  (((2 * s + half) ^ i7) << 4));
                ldsm4(d0, d1, d2, d3, addr);
                mma_bf16(sacc[2 * np], qa[s], d0, d1);
                mma_bf16(sacc[2 * np + 1], qa[s], d2, d3);
            }
        }

        // ---- causal mask (diagonal tile only) ----
        if (kt == qt) {
            const int row0 = wid * 16 + gid;
            const int row1 = row0 + 8;
#pragma unroll
            for (int n = 0; n < 8; n++) {
                int c = 8 * n + 2 * qid;
                if (c > row0)     sacc[n][0] = -CUDART_INF_F;
                if (c + 1 > row0) sacc[n][1] = -CUDART_INF_F;
                if (c > row1)     sacc[n][2] = -CUDART_INF_F;
                if (c + 1 > row1) sacc[n][3] = -CUDART_INF_F;
            }
        }

        // ---- online softmax (base-2; q pre-scaled by log2e) ----
        float t0 = -CUDART_INF_F, t1 = -CUDART_INF_F;
#pragma unroll
        for (int n = 0; n < 8; n++) {
            t0 = fmaxf(t0, fmaxf(sacc[n][0], sacc[n][1]));
            t1 = fmaxf(t1, fmaxf(sacc[n][2], sacc[n][3]));
        }
        t0 = fmaxf(t0, __shfl_xor_sync(0xffffffffu, t0, 1));
        t0 = fmaxf(t0, __shfl_xor_sync(0xffffffffu, t0, 2));
        t1 = fmaxf(t1, __shfl_xor_sync(0xffffffffu, t1, 1));
        t1 = fmaxf(t1, __shfl_xor_sync(0xffffffffu, t1, 2));

        const float mn0 = fmaxf(m0, t0);
        const float mn1 = fmaxf(m1, t1);
        const float corr0 = ex2f(m0 - mn0);
        const float corr1 = ex2f(m1 - mn1);
        m0 = mn0; m1 = mn1;

#pragma unroll
        for (int n = 0; n < 8; n++) {
            oacc[n][0] *= corr0; oacc[n][1] *= corr0;
            oacc[n][2] *= corr1; oacc[n][3] *= corr1;
        }
        lacc[0] *= corr0;
        lacc[2] *= corr1;

        // ---- P = exp2(S - m) as fp16 A-fragments (2 exps per MUFU) ----
        uint32_t pu[4][4];
#pragma unroll
        for (int s = 0; s < 4; s++) {
            pu[s][0] = ex2_f16x2(sacc[2 * s][1] - mn0, sacc[2 * s][0] - mn0);
            pu[s][1] = ex2_f16x2(sacc[2 * s][3] - mn1, sacc[2 * s][2] - mn1);
            pu[s][2] = ex2_f16x2(sacc[2 * s + 1][1] - mn0, sacc[2 * s + 1][0] - mn0);
            pu[s][3] = ex2_f16x2(sacc[2 * s + 1][3] - mn1, sacc[2 * s + 1][2] - mn1);
        }

        // ---- l += P @ ones (row sums via tensor core) ----
#pragma unroll
        for (int s = 0; s < 4; s++)
            mma_f16(lacc, pu[s], ONE2, ONE2);

        // ---- O += P V (f16) ----
#pragma unroll
        for (int nd = 0; nd < 4; nd++) {
#pragma unroll
            for (int s = 0; s < 4; s++) {
                uint32_t d0, d1, d2, d3;
                int keyv = 16 * s + 8 * half + i7;
                unsigned addr = vbuf + (unsigned)(keyv * 128 +
                                                  (((2 * nd + koct) ^ i7) << 4));
                ldsm4t(d0, d1, d2, d3, addr);
                mma_f16(oacc[2 * nd], pu[s], d0, d1);
                mma_f16(oacc[2 * nd + 1], pu[s], d2, d3);
            }
        }
        __syncthreads();
    }

    // ---- epilogue: l is already complete per-row (ones-column trick) ----
    const float inv0 = 1.f / lacc[0];
    const float inv1 = 1.f / lacc[2];

    const int row0 = qt * 64 + wid * 16 + gid;
    const int row1 = row0 + 8;
    const size_t base0 = (size_t)(b * TLEN + row0) * DMODEL + h * DHEAD + 2 * qid;
    const size_t base1 = (size_t)(b * TLEN + row1) * DMODEL + h * DHEAD + 2 * qid;
#pragma unroll
    for (int nd = 0; nd < 8; nd++) {
        float2 x0 = *(const float2*)(x + base0 + 8 * nd);
        float2 x1 = *(const float2*)(x + base1 + 8 * nd);
        float2 r0, r1;
        r0.x = x0.x + oacc[nd][0] * inv0;
        r0.y = x0.y + oacc[nd][1] * inv0;
        r1.x = x1.x + oacc[nd][2] * inv1;
        r1.y = x1.y + oacc[nd][3] * inv1;
        *(float2*)(out + base0 + 8 * nd) = r0;
        *(float2*)(out + base1 + 8 * nd) = r1;
    }
}

extern "C" void kernel_launch(void* const* d_in, const int* in_sizes, int n_in,
                              void* d_out, int out_size) {
    const float* x  = (const float*)d_in[0];   // [B,T,D]
    const float* k  = (const float*)d_in[1];   // [B,H,T,DH]
    const float* v  = (const float*)d_in[2];   // [B,H,T,DH]
    const float* Wq = (const float*)d_in[3];   // [D,D]
    float* out = (float*)d_out;                // [B,T,D]

    convert_all<<<(3 * N4X + N4W) / 256, 256>>>(x, k, v, Wq);

    cudaFuncSetAttribute(qgemm_kernel, cudaFuncAttributeMaxDynamicSharedMemorySize,
                         GEMM_SMEM);
    dim3 g1(DMODEL / 128, (BSZ * TLEN) / 128); // (8, 32)
    qgemm_kernel<<<g1, 256, GEMM_SMEM>>>();

    dim3 g2(TLEN / 64, HN, BSZ);               // (32, 16, 2)
    attn_kernel<<<g2, 128>>>(x, out);
}